// round 9
// baseline (speedup 1.0000x reference)
#include <cuda_runtime.h>
#include <cuda_bf16.h>
#include <cuda_fp8.h>
#include <math.h>

#define HID   1024
#define VOCAB 32000
#define SEQ   64
#define NL    2
#define BOS   1
#define GRID  592          // 4 blocks per SM exactly (148 SMs)
#define LBLK  512          // blocks owning LSTM units (2 units each)
#define NT    256

#define W_SCALE  64.0f
#define W_INV    (1.0f / 64.0f)

// ---------------- device scratch ----------------
__device__ float d_h0[2][HID];
__device__ float d_h1[2][HID];
__device__ float d_logits[VOCAB];
__device__ unsigned char d_Wf8[(size_t)VOCAB * HID];   // fp8 out_W
// 0=eWih0 1=eWhh0 2=eWih1 3=eWhh1 4=dWih0 5=dWhh0 6=dWih1 7=dWhh1
__device__ unsigned char d_Lf8[8][(size_t)4 * HID * HID];
__device__ float d_pmax[GRID];
__device__ float d_psum[GRID];
__device__ int   d_pidx[GRID];
__device__ unsigned int d_count = 0;
__device__ int   d_token;
__device__ float d_M, d_logS;
__device__ unsigned int g_gen = 0;
__device__ unsigned int g_cnt = 0;

// ---------------- fp32 -> fp8 conversion ----------------
__device__ __forceinline__ uint4 cvt16_fp8(const float4* s4, size_t i) {
    __nv_fp8x2_storage_t r[8];
#pragma unroll
    for (int k = 0; k < 4; k++) {
        float4 a = s4[4 * i + k];
        float2 lo = make_float2(a.x * W_SCALE, a.y * W_SCALE);
        float2 hi = make_float2(a.z * W_SCALE, a.w * W_SCALE);
        r[2 * k + 0] = __nv_cvt_float2_to_fp8x2(lo, __NV_SATFINITE, __NV_E4M3);
        r[2 * k + 1] = __nv_cvt_float2_to_fp8x2(hi, __NV_SATFINITE, __NV_E4M3);
    }
    return *(uint4*)r;
}

__global__ void __launch_bounds__(256)
convert_w_kernel(const float* __restrict__ W)
{
    size_t i = (size_t)blockIdx.x * 256 + threadIdx.x;
    ((uint4*)d_Wf8)[i] = cvt16_fp8((const float4*)W, i);
}

__global__ void __launch_bounds__(256)
convert_lstm_kernel(const float* __restrict__ eWih, const float* __restrict__ eWhh,
                    const float* __restrict__ dWih, const float* __restrict__ dWhh)
{
    const size_t WOFF = (size_t)4 * HID * HID;
    int m = blockIdx.y;
    const float* src;
    switch (m) {
        case 0: src = eWih;        break;
        case 1: src = eWhh;        break;
        case 2: src = eWih + WOFF; break;
        case 3: src = eWhh + WOFF; break;
        case 4: src = dWih;        break;
        case 5: src = dWhh;        break;
        case 6: src = dWih + WOFF; break;
        default: src = dWhh + WOFF; break;
    }
    size_t i = (size_t)blockIdx.x * 256 + threadIdx.x;
    ((uint4*)d_Lf8[m])[i] = cvt16_fp8((const float4*)src, i);
}

// ---------------- helpers ----------------
__device__ __forceinline__ float sigmoidf_(float x) {
    return 1.0f / (1.0f + expf(-x));
}

__device__ __forceinline__ void gsync() {
    __syncthreads();
    if (threadIdx.x == 0) {
        __threadfence();
        unsigned int gen = *(volatile unsigned int*)&g_gen;
        if (atomicAdd(&g_cnt, 1u) == GRID - 1) {
            *(volatile unsigned int*)&g_cnt = 0u;
            __threadfence();
            *(volatile unsigned int*)&g_gen = gen + 1;
        } else {
            while (*(volatile unsigned int*)&g_gen == gen) __nanosleep(32);
            __threadfence();
        }
    }
    __syncthreads();
}

__device__ __forceinline__ void stage_T16(float (*dst)[64], const float* src) {
    float4 v = __ldcg(((const float4*)src) + threadIdx.x);
    int c = threadIdx.x * 4;
    dst[(c + 0) & 15][c >> 4] = v.x;
    dst[(c + 1) & 15][c >> 4] = v.y;
    dst[(c + 2) & 15][c >> 4] = v.z;
    dst[(c + 3) & 15][c >> 4] = v.w;
}

__device__ __forceinline__ float dot_fp8(const unsigned char* Wr,
                                         const float (*sv)[64], int lane)
{
    const uint4* w4 = (const uint4*)Wr;
    float acc = 0.f;
#pragma unroll
    for (int i = 0; i < 2; i++) {
        int idx = i * 32 + lane;
        uint4 wv = w4[idx];
        const __nv_fp8x2_storage_t* p = (const __nv_fp8x2_storage_t*)&wv;
#pragma unroll
        for (int k = 0; k < 8; k++) {
            __half2_raw hr = __nv_cvt_fp8x2_to_halfraw2(p[k], __NV_E4M3);
            float2 f = __half22float2(*(__half2*)&hr);
            acc += f.x * sv[2 * k][idx] + f.y * sv[2 * k + 1][idx];
        }
    }
    return acc;
}

__device__ __forceinline__ float warp_sum(float v) {
#pragma unroll
    for (int off = 16; off; off >>= 1)
        v += __shfl_xor_sync(0xffffffffu, v, off);
    return v;
}

__device__ __forceinline__ void lse_merge(float& m1, float& s1, int& i1,
                                          float m2, float s2, int i2)
{
    if (m2 > m1)      { s1 = s1 * expf(m1 - m2) + s2; m1 = m2; i1 = i2; }
    else if (m2 == m1){ s1 += s2; if (i2 < i1) i1 = i2; }
    else              { s1 += s2 * expf(m2 - m1); }
}

// pointwise with precomputed recurrent part sgh (per-block smem)
__device__ __forceinline__ void lstm_update2(const float* sg, const float* sgh,
                                             float* c_state, float* h_out,
                                             int un, int tid2,
                                             const float* bih, const float* bhh)
{
    float gi = sg[0 + tid2] + sgh[0 + tid2] + bih[0 * HID + un] + bhh[0 * HID + un];
    float gf = sg[2 + tid2] + sgh[2 + tid2] + bih[1 * HID + un] + bhh[1 * HID + un];
    float gg = sg[4 + tid2] + sgh[4 + tid2] + bih[2 * HID + un] + bhh[2 * HID + un];
    float go = sg[6 + tid2] + sgh[6 + tid2] + bih[3 * HID + un] + bhh[3 * HID + un];
    float i_ = sigmoidf_(gi);
    float f_ = sigmoidf_(gf);
    float g_ = tanhf(gg);
    float o_ = sigmoidf_(go);
    float cn = f_ * (*c_state) + i_ * g_;
    *c_state = cn;
    *h_out   = o_ * tanhf(cn);
}

// ---------------- persistent seq2seq kernel ----------------
__global__ void __launch_bounds__(NT, 4)
seq2seq_kernel(const int* __restrict__ src,
               const float* __restrict__ emb_enc,
               const float* __restrict__ enc_bih, const float* __restrict__ enc_bhh,
               const float* __restrict__ emb_dec,
               const float* __restrict__ dec_bih, const float* __restrict__ dec_bhh,
               const float* __restrict__ out_b,
               float* __restrict__ out)
{
    __shared__ float sxt0[16][64], sht0[16][64];
    __shared__ float sxt1[16][64], sht1[16][64];
    __shared__ float sg0[8], sg1[8];
    __shared__ float sgh0[8], sgh1[8];     // recurrent-part gate partials (persist)
    __shared__ float sc[NL][2];
    __shared__ float swm[8], sws[8];
    __shared__ int   swi[8];
    __shared__ float fm[NT], fs[NT];
    __shared__ int   fi[NT];
    __shared__ int   sflag;

    const int tid  = threadIdx.x;
    const int wib  = tid >> 5;
    const int lane = tid & 31;
    const int bx   = blockIdx.x;
    const bool act = (bx < LBLK);          // block owns LSTM units

    {
        int gid = bx * NT + tid;
        if (gid < 2 * HID) { ((float*)d_h0)[gid] = 0.0f; ((float*)d_h1)[gid] = 0.0f; }
        if (tid < 2) { sc[0][tid] = 0.0f; sc[1][tid] = 0.0f; }
    }
    gsync();

    const int u    = wib & 1;
    const int gate = wib >> 1;
    const int unit = bx * 2 + u;
    const size_t row_off = (size_t)(gate * HID + unit) * HID;
    const size_t BOFF = (size_t)4 * HID;

    // ================= encoder: wavefront over layers =================
    for (int k = 0; k <= SEQ; k++) {
        const bool doL0 = act && (k < SEQ);
        const bool doL1 = act && (k >= 1);

        if (doL0) {
            stage_T16(sxt0, emb_enc + (size_t)src[k] * HID);
            stage_T16(sht0, &d_h0[k & 1][0]);
        }
        if (doL1) {
            stage_T16(sxt1, &d_h0[k & 1][0]);
            stage_T16(sht1, &d_h1[(k - 1) & 1][0]);
        }
        __syncthreads();

        float acc0 = 0.f, acc1 = 0.f, accp = 0.f;
        if (doL0) {
            acc0 = dot_fp8(d_Lf8[0] + row_off, sxt0, lane)
                 + dot_fp8(d_Lf8[1] + row_off, sht0, lane);
        }
        if (doL1) {
            acc1 = dot_fp8(d_Lf8[2] + row_off, sxt1, lane)
                 + dot_fp8(d_Lf8[3] + row_off, sht1, lane);
        }
        if (act && k == SEQ)   // seed decoder: dWhh0 @ h0_final (in sxt1)
            accp = dot_fp8(d_Lf8[5] + row_off, sxt1, lane);

        acc0 = warp_sum(acc0) * W_INV;
        acc1 = warp_sum(acc1) * W_INV;
        if (act && k == SEQ) {
            accp = warp_sum(accp) * W_INV;
            if (lane == 0) sgh0[wib] = accp;
        }
        if (lane == 0) { sg0[wib] = acc0; sg1[wib] = acc1; }
        __syncthreads();

        if (tid < 2 && doL0) {
            float gi = sg0[0 + tid] + enc_bih[0 * HID + unit - u + tid] + enc_bhh[0 * HID + unit - u + tid];
            // (use explicit un below instead)
        }
        if (tid < 2 && doL0) {
            int un = bx * 2 + tid;
            float gi = sg0[0 + tid] + enc_bih[0 * HID + un] + enc_bhh[0 * HID + un];
            float gf = sg0[2 + tid] + enc_bih[1 * HID + un] + enc_bhh[1 * HID + un];
            float gg = sg0[4 + tid] + enc_bih[2 * HID + un] + enc_bhh[2 * HID + un];
            float go = sg0[6 + tid] + enc_bih[3 * HID + un] + enc_bhh[3 * HID + un];
            float i_ = sigmoidf_(gi), f_ = sigmoidf_(gf);
            float g_ = tanhf(gg),     o_ = sigmoidf_(go);
            float cn = f_ * sc[0][tid] + i_ * g_;
            sc[0][tid] = cn;
            d_h0[(k + 1) & 1][un] = o_ * tanhf(cn);
        }
        if (tid >= 2 && tid < 4 && doL1) {
            int t2 = tid - 2;
            int un = bx * 2 + t2;
            float gi = sg1[0 + t2] + enc_bih[BOFF + 0 * HID + un] + enc_bhh[BOFF + 0 * HID + un];
            float gf = sg1[2 + t2] + enc_bih[BOFF + 1 * HID + un] + enc_bhh[BOFF + 1 * HID + un];
            float gg = sg1[4 + t2] + enc_bih[BOFF + 2 * HID + un] + enc_bhh[BOFF + 2 * HID + un];
            float go = sg1[6 + t2] + enc_bih[BOFF + 3 * HID + un] + enc_bhh[BOFF + 3 * HID + un];
            float i_ = sigmoidf_(gi), f_ = sigmoidf_(gf);
            float g_ = tanhf(gg),     o_ = sigmoidf_(go);
            float cn = f_ * sc[1][t2] + i_ * g_;
            sc[1][t2] = cn;
            d_h1[k & 1][un] = o_ * tanhf(cn);
        }
        gsync();
    }
    // final: h0 = d_h0[0], h1 = d_h1[0]; sgh0 = dWhh0@h0_final

    // ================= decoder =================
    for (int t = 0; t < SEQ; t++) {
        const int pw = (t + 1) & 1;

        // ---------- phase A: L0 Wih dot (+ prev logp write; t=0: seed sgh1) ----------
        if (t > 0) {
            int gid = bx * NT + tid;
            if (gid < VOCAB)
                out[(size_t)(t - 1) * VOCAB + gid] =
                    __ldcg(&d_logits[gid]) - __ldcg(&d_M) - __ldcg(&d_logS);
        }
        {
            int tok = (t == 0) ? BOS : __ldcg(&d_token);
            if (act) {
                stage_T16(sxt0, emb_dec + (size_t)tok * HID);
                if (t == 0) stage_T16(sht0, &d_h1[0][0]);
            }
            __syncthreads();

            float acc = 0.f, accp = 0.f;
            if (act) {
                acc = dot_fp8(d_Lf8[4] + row_off, sxt0, lane);
                if (t == 0) accp = dot_fp8(d_Lf8[7] + row_off, sht0, lane);
            }
            acc = warp_sum(acc) * W_INV;
            if (t == 0 && act) {
                accp = warp_sum(accp) * W_INV;
                if (lane == 0) sgh1[wib] = accp;
            }
            if (lane == 0) sg0[wib] = acc;
            __syncthreads();
            if (tid < 2 && act)
                lstm_update2(sg0, sgh0, &sc[0][tid], &d_h0[pw][bx * 2 + tid],
                             bx * 2 + tid, tid, dec_bih, dec_bhh);
            gsync();
        }

        // ---------- phase B: L1 Wih dot ----------
        {
            if (act) stage_T16(sxt1, &d_h0[pw][0]);
            __syncthreads();

            float acc = 0.f;
            if (act) acc = dot_fp8(d_Lf8[6] + row_off, sxt1, lane);
            acc = warp_sum(acc) * W_INV;
            if (lane == 0) sg1[wib] = acc;
            __syncthreads();
            if (tid < 2 && act)
                lstm_update2(sg1, sgh1, &sc[1][tid], &d_h1[pw][bx * 2 + tid],
                             bx * 2 + tid, tid, dec_bih + BOFF, dec_bhh + BOFF);
            gsync();
        }

        // ---------- phase C: logits + next-step Whh dots + fused finalize ----------
        {
            stage_T16(sht0, &d_h1[pw][0]);           // logits + dWhh1 dot
            if (act) stage_T16(sxt0, &d_h0[pw][0]);  // dWhh0 dot
            __syncthreads();

            // precompute recurrent parts for step t+1 (hidden under logits latency)
            if (act) {
                float g0 = dot_fp8(d_Lf8[5] + row_off, sxt0, lane);
                float g1 = dot_fp8(d_Lf8[7] + row_off, sht0, lane);
                g0 = warp_sum(g0) * W_INV;
                g1 = warp_sum(g1) * W_INV;
                if (lane == 0) { sgh0[wib] = g0; sgh1[wib] = g1; }
            }

            float m = -3.0e38f, s = 0.f;
            int   mi = 0x7fffffff;
#pragma unroll
            for (int it = 0; it < 7; it++) {
                int row = it * (GRID * 8) + bx * 8 + wib;
                if (row < VOCAB) {
                    float acc = dot_fp8(d_Wf8 + (size_t)row * HID, sht0, lane);
                    acc = warp_sum(acc) * W_INV;
                    if (lane == 0) {
                        acc += out_b[row];
                        d_logits[row] = acc;
                        if (acc > m)       { s = s * expf(m - acc) + 1.f; m = acc; mi = row; }
                        else if (acc == m) { s += 1.f; if (row < mi) mi = row; }
                        else               { s += expf(acc - m); }
                    }
                }
            }
            if (lane == 0) { swm[wib] = m; sws[wib] = s; swi[wib] = mi; }
            __syncthreads();

            unsigned int gen = 0;
            if (tid == 0) {
                float bm = swm[0], bs = sws[0]; int bi = swi[0];
#pragma unroll
                for (int k = 1; k < 8; k++) lse_merge(bm, bs, bi, swm[k], sws[k], swi[k]);
                d_pmax[bx] = bm;
                d_psum[bx] = bs;
                d_pidx[bx] = bi;
                gen = *(volatile unsigned int*)&g_gen;
                __threadfence();
                unsigned int c = atomicAdd(&d_count, 1u);
                sflag = (c == GRID - 1) ? 1 : 0;
            }
            __syncthreads();

            if (sflag) {
                float m2 = -3.0e38f, s2 = 0.f; int i2 = 0x7fffffff;
                for (int k = tid; k < GRID; k += NT)
                    lse_merge(m2, s2, i2, __ldcg(&d_pmax[k]), __ldcg(&d_psum[k]),
                              __ldcg(&d_pidx[k]));
                fm[tid] = m2; fs[tid] = s2; fi[tid] = i2;
                __syncthreads();
                for (int st = NT / 2; st; st >>= 1) {
                    if (tid < st)
                        lse_merge(fm[tid], fs[tid], fi[tid],
                                  fm[tid + st], fs[tid + st], fi[tid + st]);
                    __syncthreads();
                }
                if (tid == 0) {
                    d_M     = fm[0];
                    d_logS  = logf(fs[0]);
                    d_token = fi[0];
                    *(volatile unsigned int*)&d_count = 0u;
                    __threadfence();
                    *(volatile unsigned int*)&g_gen = gen + 1;
                }
            } else {
                if (tid == 0) {
                    while (*(volatile unsigned int*)&g_gen == gen) __nanosleep(32);
                    __threadfence();
                }
            }
            __syncthreads();
        }
    }

    {
        int gid = bx * NT + tid;
        if (gid < VOCAB)
            out[(size_t)(SEQ - 1) * VOCAB + gid] =
                __ldcg(&d_logits[gid]) - __ldcg(&d_M) - __ldcg(&d_logS);
    }
}

// ---------------- host orchestration ----------------
extern "C" void kernel_launch(void* const* d_in, const int* in_sizes, int n_in,
                              void* d_out, int out_size)
{
    (void)in_sizes; (void)n_in; (void)out_size;
    const int*   src     = (const int*)  d_in[0];
    const float* emb_enc = (const float*)d_in[2];
    const float* enc_Wih = (const float*)d_in[3];
    const float* enc_Whh = (const float*)d_in[4];
    const float* enc_bih = (const float*)d_in[5];
    const float* enc_bhh = (const float*)d_in[6];
    const float* emb_dec = (const float*)d_in[7];
    const float* dec_Wih = (const float*)d_in[8];
    const float* dec_Whh = (const float*)d_in[9];
    const float* dec_bih = (const float*)d_in[10];
    const float* dec_bhh = (const float*)d_in[11];
    const float* out_W   = (const float*)d_in[12];
    const float* out_b   = (const float*)d_in[13];
    float* out = (float*)d_out;

    convert_w_kernel<<<(int)((size_t)VOCAB * HID / 16 / 256), 256>>>(out_W);
    convert_lstm_kernel<<<dim3(1024, 8), 256>>>(enc_Wih, enc_Whh, dec_Wih, dec_Whh);

    seq2seq_kernel<<<GRID, NT>>>(src, emb_enc, enc_bih, enc_bhh,
                                 emb_dec, dec_bih, dec_bhh, out_b, out);
}

// round 10
// speedup vs baseline: 1.0256x; 1.0256x over previous
#include <cuda_runtime.h>
#include <cuda_bf16.h>
#include <cuda_fp8.h>
#include <math.h>

#define HID   1024
#define VOCAB 32000
#define SEQ   64
#define NL    2
#define BOS   1
#define GRID  148          // one block per SM
#define LBLK  128          // blocks owning LSTM units (8 units each)
#define NT    1024

#define W_SCALE  64.0f
#define W_INV    (1.0f / 64.0f)

// ---------------- device scratch ----------------
__device__ float d_h0[2][HID];
__device__ float d_h1[2][HID];
__device__ float d_logits[VOCAB];
__device__ unsigned char d_Wf8[(size_t)VOCAB * HID];   // fp8 out_W
// 0=eWih0 1=eWhh0 2=eWih1 3=eWhh1 4=dWih0 5=dWhh0 6=dWih1 7=dWhh1
__device__ unsigned char d_Lf8[8][(size_t)4 * HID * HID];
__device__ float d_pmax[GRID];
__device__ float d_psum[GRID];
__device__ int   d_pidx[GRID];
__device__ unsigned int d_count = 0;
__device__ int   d_token;
__device__ float d_M, d_logS;
__device__ unsigned int g_gen = 0;
__device__ unsigned int g_cnt = 0;

// ---------------- fp32 -> fp8 conversion ----------------
__device__ __forceinline__ uint4 cvt16_fp8(const float4* s4, size_t i) {
    __nv_fp8x2_storage_t r[8];
#pragma unroll
    for (int k = 0; k < 4; k++) {
        float4 a = s4[4 * i + k];
        float2 lo = make_float2(a.x * W_SCALE, a.y * W_SCALE);
        float2 hi = make_float2(a.z * W_SCALE, a.w * W_SCALE);
        r[2 * k + 0] = __nv_cvt_float2_to_fp8x2(lo, __NV_SATFINITE, __NV_E4M3);
        r[2 * k + 1] = __nv_cvt_float2_to_fp8x2(hi, __NV_SATFINITE, __NV_E4M3);
    }
    return *(uint4*)r;
}

__global__ void __launch_bounds__(256)
convert_w_kernel(const float* __restrict__ W)
{
    size_t i = (size_t)blockIdx.x * 256 + threadIdx.x;
    ((uint4*)d_Wf8)[i] = cvt16_fp8((const float4*)W, i);
}

__global__ void __launch_bounds__(256)
convert_lstm_kernel(const float* __restrict__ eWih, const float* __restrict__ eWhh,
                    const float* __restrict__ dWih, const float* __restrict__ dWhh)
{
    const size_t WOFF = (size_t)4 * HID * HID;
    int m = blockIdx.y;
    const float* src;
    switch (m) {
        case 0: src = eWih;        break;
        case 1: src = eWhh;        break;
        case 2: src = eWih + WOFF; break;
        case 3: src = eWhh + WOFF; break;
        case 4: src = dWih;        break;
        case 5: src = dWhh;        break;
        case 6: src = dWih + WOFF; break;
        default: src = dWhh + WOFF; break;
    }
    size_t i = (size_t)blockIdx.x * 256 + threadIdx.x;
    ((uint4*)d_Lf8[m])[i] = cvt16_fp8((const float4*)src, i);
}

// ---------------- helpers ----------------
__device__ __forceinline__ float sigmoidf_(float x) {
    return 1.0f / (1.0f + expf(-x));
}

__device__ __forceinline__ void gsync() {
    __syncthreads();
    if (threadIdx.x == 0) {
        __threadfence();
        unsigned int gen = *(volatile unsigned int*)&g_gen;
        if (atomicAdd(&g_cnt, 1u) == GRID - 1) {
            *(volatile unsigned int*)&g_cnt = 0u;
            __threadfence();
            *(volatile unsigned int*)&g_gen = gen + 1;
        } else {
            while (*(volatile unsigned int*)&g_gen == gen) __nanosleep(32);
            __threadfence();
        }
    }
    __syncthreads();
}

// stage fp32 vector into transposed smem: dst[c & 15][c >> 4] = v[c]; NT=1024 threads
__device__ __forceinline__ void stage1024(float (*dst)[64], const float* src) {
    float v = __ldcg(src + threadIdx.x);
    dst[threadIdx.x & 15][threadIdx.x >> 4] = v;
}

// fp8 row (1024 cols = 64 uint4) dot transposed fp32 vector
__device__ __forceinline__ float dot_fp8(const unsigned char* Wr,
                                         const float (*sv)[64], int lane)
{
    const uint4* w4 = (const uint4*)Wr;
    float acc = 0.f;
#pragma unroll
    for (int i = 0; i < 2; i++) {
        int idx = i * 32 + lane;
        uint4 wv = w4[idx];
        const __nv_fp8x2_storage_t* p = (const __nv_fp8x2_storage_t*)&wv;
#pragma unroll
        for (int k = 0; k < 8; k++) {
            __half2_raw hr = __nv_cvt_fp8x2_to_halfraw2(p[k], __NV_E4M3);
            float2 f = __half22float2(*(__half2*)&hr);
            acc += f.x * sv[2 * k][idx] + f.y * sv[2 * k + 1][idx];
        }
    }
    return acc;
}

__device__ __forceinline__ float dot2_fp8(const unsigned char* Wr, const unsigned char* Ur,
                                          const float (*sx)[64], const float (*sh)[64],
                                          int lane)
{
    const uint4* w4 = (const uint4*)Wr;
    const uint4* u4 = (const uint4*)Ur;
    float acc = 0.f;
#pragma unroll
    for (int i = 0; i < 2; i++) {
        int idx = i * 32 + lane;
        uint4 wv = w4[idx];
        uint4 uv = u4[idx];
        const __nv_fp8x2_storage_t* pw = (const __nv_fp8x2_storage_t*)&wv;
        const __nv_fp8x2_storage_t* pu = (const __nv_fp8x2_storage_t*)&uv;
#pragma unroll
        for (int k = 0; k < 8; k++) {
            __half2_raw hw = __nv_cvt_fp8x2_to_halfraw2(pw[k], __NV_E4M3);
            __half2_raw hu = __nv_cvt_fp8x2_to_halfraw2(pu[k], __NV_E4M3);
            float2 fw = __half22float2(*(__half2*)&hw);
            float2 fu = __half22float2(*(__half2*)&hu);
            acc += fw.x * sx[2 * k][idx] + fw.y * sx[2 * k + 1][idx];
            acc += fu.x * sh[2 * k][idx] + fu.y * sh[2 * k + 1][idx];
        }
    }
    return acc;
}

__device__ __forceinline__ float warp_sum(float v) {
#pragma unroll
    for (int off = 16; off; off >>= 1)
        v += __shfl_xor_sync(0xffffffffu, v, off);
    return v;
}

__device__ __forceinline__ void lse_merge(float& m1, float& s1, int& i1,
                                          float m2, float s2, int i2)
{
    if (m2 > m1)      { s1 = s1 * expf(m1 - m2) + s2; m1 = m2; i1 = i2; }
    else if (m2 == m1){ s1 += s2; if (i2 < i1) i1 = i2; }
    else              { s1 += s2 * expf(m2 - m1); }
}

// pointwise update for unit `un`, gate partials sg[ul*4 + g]
__device__ __forceinline__ void lstm_update(const float* sg, int ul, float* c_state,
                                            float* h_out, int un,
                                            const float* bih, const float* bhh)
{
    float gi = sg[ul * 4 + 0] + bih[0 * HID + un] + bhh[0 * HID + un];
    float gf = sg[ul * 4 + 1] + bih[1 * HID + un] + bhh[1 * HID + un];
    float gg = sg[ul * 4 + 2] + bih[2 * HID + un] + bhh[2 * HID + un];
    float go = sg[ul * 4 + 3] + bih[3 * HID + un] + bhh[3 * HID + un];
    float i_ = sigmoidf_(gi);
    float f_ = sigmoidf_(gf);
    float g_ = tanhf(gg);
    float o_ = sigmoidf_(go);
    float cn = f_ * (*c_state) + i_ * g_;
    *c_state = cn;
    *h_out   = o_ * tanhf(cn);
}

// ---------------- persistent seq2seq kernel ----------------
__global__ void __launch_bounds__(NT, 1)
seq2seq_kernel(const int* __restrict__ src,
               const float* __restrict__ emb_enc,
               const float* __restrict__ enc_bih, const float* __restrict__ enc_bhh,
               const float* __restrict__ emb_dec,
               const float* __restrict__ dec_bih, const float* __restrict__ dec_bhh,
               const float* __restrict__ out_b,
               float* __restrict__ out)
{
    __shared__ float sxt0[16][64], sht0[16][64];
    __shared__ float sxt1[16][64], sht1[16][64];
    __shared__ float sg0[32], sg1[32];
    __shared__ float sc[NL][8];
    __shared__ float swm[32], sws[32];
    __shared__ int   swi[32];
    __shared__ float fm[256], fs[256];
    __shared__ int   fi[256];
    __shared__ int   sflag;

    const int tid  = threadIdx.x;
    const int wib  = tid >> 5;           // 0..31
    const int lane = tid & 31;
    const int bx   = blockIdx.x;
    const bool act = (bx < LBLK);        // block owns 8 LSTM units

    {
        int gid = bx * NT + tid;
        if (gid < 2 * HID) { ((float*)d_h0)[gid] = 0.0f; ((float*)d_h1)[gid] = 0.0f; }
        if (tid < 8) { sc[0][tid] = 0.0f; sc[1][tid] = 0.0f; }
    }
    gsync();

    const int ul   = wib >> 2;           // unit-local 0..7
    const int gate = wib & 3;            // 0..3
    const int unit = bx * 8 + ul;
    const size_t row_off = (size_t)(gate * HID + unit) * HID;
    const size_t BOFF = (size_t)4 * HID;

    // ================= encoder: wavefront over layers =================
    for (int k = 0; k <= SEQ; k++) {
        const bool doL0 = act && (k < SEQ);
        const bool doL1 = act && (k >= 1);

        if (doL0) {
            stage1024(sxt0, emb_enc + (size_t)src[k] * HID);
            stage1024(sht0, &d_h0[k & 1][0]);
        }
        if (doL1) {
            stage1024(sxt1, &d_h0[k & 1][0]);
            stage1024(sht1, &d_h1[(k - 1) & 1][0]);
        }
        __syncthreads();

        float acc0 = 0.f, acc1 = 0.f;
        if (doL0)
            acc0 = dot2_fp8(d_Lf8[0] + row_off, d_Lf8[1] + row_off, sxt0, sht0, lane);
        if (doL1)
            acc1 = dot2_fp8(d_Lf8[2] + row_off, d_Lf8[3] + row_off, sxt1, sht1, lane);
        acc0 = warp_sum(acc0) * W_INV;
        acc1 = warp_sum(acc1) * W_INV;
        if (lane == 0) { sg0[wib] = acc0; sg1[wib] = acc1; }
        __syncthreads();

        if (tid < 8 && doL0)
            lstm_update(sg0, tid, &sc[0][tid], &d_h0[(k + 1) & 1][bx * 8 + tid],
                        bx * 8 + tid, enc_bih, enc_bhh);
        if (tid >= 8 && tid < 16 && doL1)
            lstm_update(sg1, tid - 8, &sc[1][tid - 8], &d_h1[k & 1][bx * 8 + (tid - 8)],
                        bx * 8 + (tid - 8), enc_bih + BOFF, enc_bhh + BOFF);
        gsync();
    }
    // final: h0 = d_h0[0], h1 = d_h1[0]

    // ================= decoder =================
    for (int t = 0; t < SEQ; t++) {
        const int pr = t & 1;
        const int pw = (t + 1) & 1;

        // ---------- phase A: layer 0 (+ prev logp write) ----------
        if (t > 0) {
            int gid = bx * NT + tid;
            if (gid < VOCAB)
                out[(size_t)(t - 1) * VOCAB + gid] =
                    __ldcg(&d_logits[gid]) - __ldcg(&d_M) - __ldcg(&d_logS);
        }
        {
            int tok = (t == 0) ? BOS : __ldcg(&d_token);
            if (act) {
                stage1024(sxt0, emb_dec + (size_t)tok * HID);
                stage1024(sht0, &d_h0[pr][0]);
            }
            __syncthreads();

            float acc = 0.f;
            if (act)
                acc = dot2_fp8(d_Lf8[4] + row_off, d_Lf8[5] + row_off,
                               sxt0, sht0, lane);
            acc = warp_sum(acc) * W_INV;
            if (lane == 0) sg0[wib] = acc;
            __syncthreads();
            if (tid < 8 && act)
                lstm_update(sg0, tid, &sc[0][tid], &d_h0[pw][bx * 8 + tid],
                            bx * 8 + tid, dec_bih, dec_bhh);
            gsync();
        }

        // ---------- phase B: layer 1 ----------
        {
            if (act) {
                stage1024(sxt1, &d_h0[pw][0]);
                stage1024(sht1, &d_h1[pr][0]);
            }
            __syncthreads();

            float acc = 0.f;
            if (act)
                acc = dot2_fp8(d_Lf8[6] + row_off, d_Lf8[7] + row_off,
                               sxt1, sht1, lane);
            acc = warp_sum(acc) * W_INV;
            if (lane == 0) sg1[wib] = acc;
            __syncthreads();
            if (tid < 8 && act)
                lstm_update(sg1, tid, &sc[1][tid], &d_h1[pw][bx * 8 + tid],
                            bx * 8 + tid, dec_bih + BOFF, dec_bhh + BOFF);
            gsync();
        }

        // ---------- phase C: logits + fused finalize ----------
        {
            stage1024(sht0, &d_h1[pw][0]);
            __syncthreads();

            float m = -3.0e38f, s = 0.f;
            int   mi = 0x7fffffff;
#pragma unroll
            for (int it = 0; it < 7; it++) {
                int row = it * (GRID * 32) + bx * 32 + wib;
                if (row < VOCAB) {
                    float acc = dot_fp8(d_Wf8 + (size_t)row * HID, sht0, lane);
                    acc = warp_sum(acc) * W_INV;
                    if (lane == 0) {
                        acc += out_b[row];
                        d_logits[row] = acc;
                        if (acc > m)       { s = s * expf(m - acc) + 1.f; m = acc; mi = row; }
                        else if (acc == m) { s += 1.f; if (row < mi) mi = row; }
                        else               { s += expf(acc - m); }
                    }
                }
            }
            if (lane == 0) { swm[wib] = m; sws[wib] = s; swi[wib] = mi; }
            __syncthreads();

            unsigned int gen = 0;
            if (tid == 0) {
                float bm = swm[0], bs = sws[0]; int bi = swi[0];
#pragma unroll
                for (int k = 1; k < 32; k++) lse_merge(bm, bs, bi, swm[k], sws[k], swi[k]);
                d_pmax[bx] = bm;
                d_psum[bx] = bs;
                d_pidx[bx] = bi;
                gen = *(volatile unsigned int*)&g_gen;
                __threadfence();
                unsigned int c = atomicAdd(&d_count, 1u);
                sflag = (c == GRID - 1) ? 1 : 0;
            }
            __syncthreads();

            if (sflag) {
                // last block: finalize over GRID partials, then release barrier
                if (tid < 256) {
                    if (tid < GRID) {
                        fm[tid] = __ldcg(&d_pmax[tid]);
                        fs[tid] = __ldcg(&d_psum[tid]);
                        fi[tid] = __ldcg(&d_pidx[tid]);
                    } else {
                        fm[tid] = -3.0e38f; fs[tid] = 0.f; fi[tid] = 0x7fffffff;
                    }
                }
                __syncthreads();
                for (int st = 128; st; st >>= 1) {
                    if (tid < st)
                        lse_merge(fm[tid], fs[tid], fi[tid],
                                  fm[tid + st], fs[tid + st], fi[tid + st]);
                    __syncthreads();
                }
                if (tid == 0) {
                    d_M     = fm[0];
                    d_logS  = logf(fs[0]);
                    d_token = fi[0];
                    *(volatile unsigned int*)&d_count = 0u;
                    __threadfence();
                    *(volatile unsigned int*)&g_gen = gen + 1;
                }
            } else {
                if (tid == 0) {
                    while (*(volatile unsigned int*)&g_gen == gen) __nanosleep(32);
                    __threadfence();
                }
            }
            __syncthreads();
        }
    }

    {
        int gid = bx * NT + tid;
        if (gid < VOCAB)
            out[(size_t)(SEQ - 1) * VOCAB + gid] =
                __ldcg(&d_logits[gid]) - __ldcg(&d_M) - __ldcg(&d_logS);
    }
}

// ---------------- host orchestration ----------------
extern "C" void kernel_launch(void* const* d_in, const int* in_sizes, int n_in,
                              void* d_out, int out_size)
{
    (void)in_sizes; (void)n_in; (void)out_size;
    const int*   src     = (const int*)  d_in[0];
    const float* emb_enc = (const float*)d_in[2];
    const float* enc_Wih = (const float*)d_in[3];
    const float* enc_Whh = (const float*)d_in[4];
    const float* enc_bih = (const float*)d_in[5];
    const float* enc_bhh = (const float*)d_in[6];
    const float* emb_dec = (const float*)d_in[7];
    const float* dec_Wih = (const float*)d_in[8];
    const float* dec_Whh = (const float*)d_in[9];
    const float* dec_bih = (const float*)d_in[10];
    const float* dec_bhh = (const float*)d_in[11];
    const float* out_W   = (const float*)d_in[12];
    const float* out_b   = (const float*)d_in[13];
    float* out = (float*)d_out;

    convert_w_kernel<<<(int)((size_t)VOCAB * HID / 16 / 256), 256>>>(out_W);
    convert_lstm_kernel<<<dim3(1024, 8), 256>>>(enc_Wih, enc_Whh, dec_Wih, dec_Whh);

    seq2seq_kernel<<<GRID, NT>>>(src, emb_enc, enc_bih, enc_bhh,
                                 emb_dec, dec_bih, dec_bhh, out_b, out);
}

// round 11
// speedup vs baseline: 1.1679x; 1.1388x over previous
#include <cuda_runtime.h>
#include <cuda_fp16.h>
#include <cuda_bf16.h>
#include <cuda_fp8.h>
#include <math.h>

#define HID   1024
#define VOCAB 32000
#define SEQ   64
#define NL    2
#define BOS   1
#define GRID  148          // one block per SM
#define LBLK  128          // blocks owning LSTM units (8 units each)
#define NT    1024

#define W_SCALE  64.0f
#define W_INV    (1.0f / 64.0f)

// ---------------- device scratch ----------------
__device__ float d_h0[2][HID];
__device__ float d_h1[2][HID];
__device__ float d_logits[VOCAB];
__device__ unsigned char d_Wf8[(size_t)VOCAB * HID];   // fp8 out_W
// 0=eWih0 1=eWhh0 2=eWih1 3=eWhh1 4=dWih0 5=dWhh0 6=dWih1 7=dWhh1
__device__ unsigned char d_Lf8[8][(size_t)4 * HID * HID];
__device__ float d_pmax[GRID];
__device__ float d_psum[GRID];
__device__ int   d_pidx[GRID];
__device__ unsigned int d_count = 0;
__device__ int   d_token;
__device__ float d_M, d_logS;
__device__ unsigned int g_gen = 0;
__device__ unsigned int g_cnt = 0;

// ---------------- fp32 -> fp8 conversion ----------------
__device__ __forceinline__ uint4 cvt16_fp8(const float4* s4, size_t i) {
    __nv_fp8x2_storage_t r[8];
#pragma unroll
    for (int k = 0; k < 4; k++) {
        float4 a = s4[4 * i + k];
        float2 lo = make_float2(a.x * W_SCALE, a.y * W_SCALE);
        float2 hi = make_float2(a.z * W_SCALE, a.w * W_SCALE);
        r[2 * k + 0] = __nv_cvt_float2_to_fp8x2(lo, __NV_SATFINITE, __NV_E4M3);
        r[2 * k + 1] = __nv_cvt_float2_to_fp8x2(hi, __NV_SATFINITE, __NV_E4M3);
    }
    return *(uint4*)r;
}

__global__ void __launch_bounds__(256)
convert_w_kernel(const float* __restrict__ W)
{
    size_t i = (size_t)blockIdx.x * 256 + threadIdx.x;
    ((uint4*)d_Wf8)[i] = cvt16_fp8((const float4*)W, i);
}

__global__ void __launch_bounds__(256)
convert_lstm_kernel(const float* __restrict__ eWih, const float* __restrict__ eWhh,
                    const float* __restrict__ dWih, const float* __restrict__ dWhh)
{
    const size_t WOFF = (size_t)4 * HID * HID;
    int m = blockIdx.y;
    const float* src;
    switch (m) {
        case 0: src = eWih;        break;
        case 1: src = eWhh;        break;
        case 2: src = eWih + WOFF; break;
        case 3: src = eWhh + WOFF; break;
        case 4: src = dWih;        break;
        case 5: src = dWhh;        break;
        case 6: src = dWih + WOFF; break;
        default: src = dWhh + WOFF; break;
    }
    size_t i = (size_t)blockIdx.x * 256 + threadIdx.x;
    ((uint4*)d_Lf8[m])[i] = cvt16_fp8((const float4*)src, i);
}

// ---------------- helpers ----------------
__device__ __forceinline__ float sigmoidf_(float x) {
    return 1.0f / (1.0f + expf(-x));
}

__device__ __forceinline__ void gsync() {
    __syncthreads();
    if (threadIdx.x == 0) {
        __threadfence();
        unsigned int gen = *(volatile unsigned int*)&g_gen;
        if (atomicAdd(&g_cnt, 1u) == GRID - 1) {
            *(volatile unsigned int*)&g_cnt = 0u;
            __threadfence();
            *(volatile unsigned int*)&g_gen = gen + 1;
        } else {
            while (*(volatile unsigned int*)&g_gen == gen) __nanosleep(32);
            __threadfence();
        }
    }
    __syncthreads();
}

// stage fp32 vector (coherent read) into half2 smem: shv[i] = (v[2i], v[2i+1])
__device__ __forceinline__ void stage_h2(half2* dst, const float* src) {
    if (threadIdx.x < 512) {
        float2 v = __ldcg(((const float2*)src) + threadIdx.x);
        dst[threadIdx.x] = __float22half2_rn(v);
    }
}
// read-only (never written during kernel) variant
__device__ __forceinline__ void stage_h2_ro(half2* dst, const float* src) {
    if (threadIdx.x < 512) {
        float2 v = ((const float2*)src)[threadIdx.x];
        dst[threadIdx.x] = __float22half2_rn(v);
    }
}

// load lane's 16 half2 (cols [16L..16L+15] and [16(L+32)..]) into 4 uint4 regs
__device__ __forceinline__ void load_vec(uint4* hv, const half2* shv, int lane) {
    const uint4* s4 = (const uint4*)shv;
    hv[0] = s4[lane * 2];
    hv[1] = s4[lane * 2 + 1];
    hv[2] = s4[(lane + 32) * 2];
    hv[3] = s4[(lane + 32) * 2 + 1];
}

// fp8 row (1024 cols) dot register-cached half2 vector
__device__ __forceinline__ float dot_fp8h(const unsigned char* Wr,
                                          const uint4* hv, int lane)
{
    const uint4* w4 = (const uint4*)Wr;
    uint4 w0 = w4[lane];
    uint4 w1 = w4[lane + 32];
    const __nv_fp8x2_storage_t* p0 = (const __nv_fp8x2_storage_t*)&w0;
    const __nv_fp8x2_storage_t* p1 = (const __nv_fp8x2_storage_t*)&w1;
    const half2* h = (const half2*)hv;
    half2 a0 = __float2half2_rn(0.f);
    half2 a1 = __float2half2_rn(0.f);
#pragma unroll
    for (int k = 0; k < 8; k++) {
        __half2_raw r0 = __nv_cvt_fp8x2_to_halfraw2(p0[k], __NV_E4M3);
        __half2_raw r1 = __nv_cvt_fp8x2_to_halfraw2(p1[k], __NV_E4M3);
        a0 = __hfma2(*(half2*)&r0, h[k],     a0);
        a1 = __hfma2(*(half2*)&r1, h[8 + k], a1);
    }
    float2 f0 = __half22float2(a0);
    float2 f1 = __half22float2(a1);
    return (f0.x + f0.y) + (f1.x + f1.y);
}

// convenience: load vector regs then dot (for single-use vectors)
__device__ __forceinline__ float dotv(const unsigned char* Wr,
                                      const half2* shv, int lane)
{
    uint4 hv[4];
    load_vec(hv, shv, lane);
    return dot_fp8h(Wr, hv, lane);
}

__device__ __forceinline__ float warp_sum(float v) {
#pragma unroll
    for (int off = 16; off; off >>= 1)
        v += __shfl_xor_sync(0xffffffffu, v, off);
    return v;
}

__device__ __forceinline__ void lse_merge(float& m1, float& s1, int& i1,
                                          float m2, float s2, int i2)
{
    if (m2 > m1)      { s1 = s1 * expf(m1 - m2) + s2; m1 = m2; i1 = i2; }
    else if (m2 == m1){ s1 += s2; if (i2 < i1) i1 = i2; }
    else              { s1 += s2 * expf(m2 - m1); }
}

__device__ __forceinline__ void lstm_update(const float* sg, int ul, float* c_state,
                                            float* h_out, int un,
                                            const float* bih, const float* bhh)
{
    float gi = sg[ul * 4 + 0] + bih[0 * HID + un] + bhh[0 * HID + un];
    float gf = sg[ul * 4 + 1] + bih[1 * HID + un] + bhh[1 * HID + un];
    float gg = sg[ul * 4 + 2] + bih[2 * HID + un] + bhh[2 * HID + un];
    float go = sg[ul * 4 + 3] + bih[3 * HID + un] + bhh[3 * HID + un];
    float i_ = sigmoidf_(gi);
    float f_ = sigmoidf_(gf);
    float g_ = tanhf(gg);
    float o_ = sigmoidf_(go);
    float cn = f_ * (*c_state) + i_ * g_;
    *c_state = cn;
    *h_out   = o_ * tanhf(cn);
}

// ---------------- persistent seq2seq kernel ----------------
__global__ void __launch_bounds__(NT, 1)
seq2seq_kernel(const int* __restrict__ src,
               const float* __restrict__ emb_enc,
               const float* __restrict__ enc_bih, const float* __restrict__ enc_bhh,
               const float* __restrict__ emb_dec,
               const float* __restrict__ dec_bih, const float* __restrict__ dec_bhh,
               const float* __restrict__ out_b,
               float* __restrict__ out)
{
    __shared__ half2 sx0[512], sh0[512];   // layer-0 x, h (2 KB each)
    __shared__ half2 sx1[512], sh1[512];   // layer-1 x, h
    __shared__ float sg0[32], sg1[32];
    __shared__ float sc[NL][8];
    __shared__ float swm[32], sws[32];
    __shared__ int   swi[32];
    __shared__ float fm[256], fs[256];
    __shared__ int   fi[256];
    __shared__ int   sflag;

    const int tid  = threadIdx.x;
    const int wib  = tid >> 5;           // 0..31
    const int lane = tid & 31;
    const int bx   = blockIdx.x;
    const bool act = (bx < LBLK);        // block owns 8 LSTM units

    {
        int gid = bx * NT + tid;
        if (gid < 2 * HID) { ((float*)d_h0)[gid] = 0.0f; ((float*)d_h1)[gid] = 0.0f; }
        if (tid < 8) { sc[0][tid] = 0.0f; sc[1][tid] = 0.0f; }
    }
    gsync();

    const int ul   = wib >> 2;           // unit-local 0..7
    const int gate = wib & 3;            // 0..3
    const int unit = bx * 8 + ul;
    const size_t row_off = (size_t)(gate * HID + unit) * HID;
    const size_t BOFF = (size_t)4 * HID;

    // ================= encoder: wavefront over layers =================
    for (int k = 0; k <= SEQ; k++) {
        const bool doL0 = act && (k < SEQ);
        const bool doL1 = act && (k >= 1);

        if (doL0) {
            stage_h2_ro(sx0, emb_enc + (size_t)src[k] * HID);
            stage_h2(sh0, &d_h0[k & 1][0]);
        }
        if (doL1) {
            stage_h2(sx1, &d_h0[k & 1][0]);
            stage_h2(sh1, &d_h1[(k - 1) & 1][0]);
        }
        __syncthreads();

        float acc0 = 0.f, acc1 = 0.f;
        if (doL0)
            acc0 = dotv(d_Lf8[0] + row_off, sx0, lane)
                 + dotv(d_Lf8[1] + row_off, sh0, lane);
        if (doL1)
            acc1 = dotv(d_Lf8[2] + row_off, sx1, lane)
                 + dotv(d_Lf8[3] + row_off, sh1, lane);
        acc0 = warp_sum(acc0) * W_INV;
        acc1 = warp_sum(acc1) * W_INV;
        if (lane == 0) { sg0[wib] = acc0; sg1[wib] = acc1; }
        __syncthreads();

        if (tid < 8 && doL0)
            lstm_update(sg0, tid, &sc[0][tid], &d_h0[(k + 1) & 1][bx * 8 + tid],
                        bx * 8 + tid, enc_bih, enc_bhh);
        if (tid >= 8 && tid < 16 && doL1)
            lstm_update(sg1, tid - 8, &sc[1][tid - 8], &d_h1[k & 1][bx * 8 + (tid - 8)],
                        bx * 8 + (tid - 8), enc_bih + BOFF, enc_bhh + BOFF);
        gsync();
    }
    // final: h0 = d_h0[0], h1 = d_h1[0]

    // ================= decoder =================
    for (int t = 0; t < SEQ; t++) {
        const int pr = t & 1;
        const int pw = (t + 1) & 1;

        // ---------- phase A: layer 0 (+ prev logp write) ----------
        if (t > 0) {
            int gid = bx * NT + tid;
            if (gid < VOCAB)
                out[(size_t)(t - 1) * VOCAB + gid] =
                    __ldcg(&d_logits[gid]) - __ldcg(&d_M) - __ldcg(&d_logS);
        }
        {
            int tok = (t == 0) ? BOS : __ldcg(&d_token);
            if (act) {
                stage_h2_ro(sx0, emb_dec + (size_t)tok * HID);
                stage_h2(sh0, &d_h0[pr][0]);
            }
            __syncthreads();

            float acc = 0.f;
            if (act)
                acc = dotv(d_Lf8[4] + row_off, sx0, lane)
                    + dotv(d_Lf8[5] + row_off, sh0, lane);
            acc = warp_sum(acc) * W_INV;
            if (lane == 0) sg0[wib] = acc;
            __syncthreads();
            if (tid < 8 && act)
                lstm_update(sg0, tid, &sc[0][tid], &d_h0[pw][bx * 8 + tid],
                            bx * 8 + tid, dec_bih, dec_bhh);
            gsync();
        }

        // ---------- phase B: layer 1 ----------
        {
            if (act) {
                stage_h2(sx1, &d_h0[pw][0]);
                stage_h2(sh1, &d_h1[pr][0]);
            }
            __syncthreads();

            float acc = 0.f;
            if (act)
                acc = dotv(d_Lf8[6] + row_off, sx1, lane)
                    + dotv(d_Lf8[7] + row_off, sh1, lane);
            acc = warp_sum(acc) * W_INV;
            if (lane == 0) sg1[wib] = acc;
            __syncthreads();
            if (tid < 8 && act)
                lstm_update(sg1, tid, &sc[1][tid], &d_h1[pw][bx * 8 + tid],
                            bx * 8 + tid, dec_bih + BOFF, dec_bhh + BOFF);
            gsync();
        }

        // ---------- phase C: logits + fused finalize ----------
        {
            stage_h2(sh0, &d_h1[pw][0]);
            __syncthreads();

            uint4 hv[4];
            load_vec(hv, sh0, lane);     // register-cached across all 7 rows

            float m = -3.0e38f, s = 0.f;
            int   mi = 0x7fffffff;
#pragma unroll
            for (int it = 0; it < 7; it++) {
                int row = it * (GRID * 32) + bx * 32 + wib;
                if (row < VOCAB) {
                    float acc = dot_fp8h(d_Wf8 + (size_t)row * HID, hv, lane);
                    acc = warp_sum(acc) * W_INV;
                    if (lane == 0) {
                        acc += out_b[row];
                        d_logits[row] = acc;
                        if (acc > m)       { s = s * expf(m - acc) + 1.f; m = acc; mi = row; }
                        else if (acc == m) { s += 1.f; if (row < mi) mi = row; }
                        else               { s += expf(acc - m); }
                    }
                }
            }
            if (lane == 0) { swm[wib] = m; sws[wib] = s; swi[wib] = mi; }
            __syncthreads();

            unsigned int gen = 0;
            if (tid == 0) {
                float bm = swm[0], bs = sws[0]; int bi = swi[0];
#pragma unroll
                for (int k = 1; k < 32; k++) lse_merge(bm, bs, bi, swm[k], sws[k], swi[k]);
                d_pmax[bx] = bm;
                d_psum[bx] = bs;
                d_pidx[bx] = bi;
                gen = *(volatile unsigned int*)&g_gen;
                __threadfence();
                unsigned int c = atomicAdd(&d_count, 1u);
                sflag = (c == GRID - 1) ? 1 : 0;
            }
            __syncthreads();

            if (sflag) {
                if (tid < 256) {
                    if (tid < GRID) {
                        fm[tid] = __ldcg(&d_pmax[tid]);
                        fs[tid] = __ldcg(&d_psum[tid]);
                        fi[tid] = __ldcg(&d_pidx[tid]);
                    } else {
                        fm[tid] = -3.0e38f; fs[tid] = 0.f; fi[tid] = 0x7fffffff;
                    }
                }
                __syncthreads();
                for (int st = 128; st; st >>= 1) {
                    if (tid < st)
                        lse_merge(fm[tid], fs[tid], fi[tid],
                                  fm[tid + st], fs[tid + st], fi[tid + st]);
                    __syncthreads();
                }
                if (tid == 0) {
                    d_M     = fm[0];
                    d_logS  = logf(fs[0]);
                    d_token = fi[0];
                    *(volatile unsigned int*)&d_count = 0u;
                    __threadfence();
                    *(volatile unsigned int*)&g_gen = gen + 1;
                }
            } else {
                if (tid == 0) {
                    while (*(volatile unsigned int*)&g_gen == gen) __nanosleep(32);
                    __threadfence();
                }
            }
            __syncthreads();
        }
    }

    {
        int gid = bx * NT + tid;
        if (gid < VOCAB)
            out[(size_t)(SEQ - 1) * VOCAB + gid] =
                __ldcg(&d_logits[gid]) - __ldcg(&d_M) - __ldcg(&d_logS);
    }
}

// ---------------- host orchestration ----------------
extern "C" void kernel_launch(void* const* d_in, const int* in_sizes, int n_in,
                              void* d_out, int out_size)
{
    (void)in_sizes; (void)n_in; (void)out_size;
    const int*   src     = (const int*)  d_in[0];
    const float* emb_enc = (const float*)d_in[2];
    const float* enc_Wih = (const float*)d_in[3];
    const float* enc_Whh = (const float*)d_in[4];
    const float* enc_bih = (const float*)d_in[5];
    const float* enc_bhh = (const float*)d_in[6];
    const float* emb_dec = (const float*)d_in[7];
    const float* dec_Wih = (const float*)d_in[8];
    const float* dec_Whh = (const float*)d_in[9];
    const float* dec_bih = (const float*)d_in[10];
    const float* dec_bhh = (const float*)d_in[11];
    const float* out_W   = (const float*)d_in[12];
    const float* out_b   = (const float*)d_in[13];
    float* out = (float*)d_out;

    convert_w_kernel<<<(int)((size_t)VOCAB * HID / 16 / 256), 256>>>(out_W);
    convert_lstm_kernel<<<dim3(1024, 8), 256>>>(enc_Wih, enc_Whh, dec_Wih, dec_Whh);

    seq2seq_kernel<<<GRID, NT>>>(src, emb_enc, enc_bih, enc_bhh,
                                 emb_dec, dec_bih, dec_bhh, out_b, out);
}

// round 12
// speedup vs baseline: 1.1732x; 1.0045x over previous
#include <cuda_runtime.h>
#include <cuda_fp16.h>
#include <cuda_bf16.h>
#include <cuda_fp8.h>
#include <math.h>

#define HID   1024
#define VOCAB 32000
#define SEQ   64
#define NL    2
#define BOS   1
#define GRID  148          // one block per SM
#define LBLK  128          // blocks owning LSTM units (8 units each)
#define NT    1024

#define W_SCALE  64.0f
#define W_INV    (1.0f / 64.0f)

// ---------------- device scratch ----------------
__device__ float d_h0[2][HID];
__device__ float d_h1[2][HID];
__device__ float d_logits[VOCAB];
__device__ unsigned char d_Wf8[(size_t)VOCAB * HID];   // fp8 out_W
// 0=eWih0 1=eWhh0 2=eWih1 3=eWhh1 4=dWih0 5=dWhh0 6=dWih1 7=dWhh1
__device__ unsigned char d_Lf8[8][(size_t)4 * HID * HID];
__device__ float d_pmax[GRID];
__device__ float d_psum[GRID];
__device__ int   d_pidx[GRID];
__device__ unsigned int d_count = 0;
__device__ int   d_token;
__device__ float d_M, d_logS;
__device__ unsigned int g_gen = 0;
__device__ unsigned int g_cnt = 0;

// ---------------- fp32 -> fp8 ----------------
__device__ __forceinline__ uint4 cvt16_fp8(const float4* s4, size_t i) {
    __nv_fp8x2_storage_t r[8];
#pragma unroll
    for (int k = 0; k < 4; k++) {
        float4 a = s4[4 * i + k];
        float2 lo = make_float2(a.x * W_SCALE, a.y * W_SCALE);
        float2 hi = make_float2(a.z * W_SCALE, a.w * W_SCALE);
        r[2 * k + 0] = __nv_cvt_float2_to_fp8x2(lo, __NV_SATFINITE, __NV_E4M3);
        r[2 * k + 1] = __nv_cvt_float2_to_fp8x2(hi, __NV_SATFINITE, __NV_E4M3);
    }
    return *(uint4*)r;
}

// ---------------- helpers ----------------
__device__ __forceinline__ float sigmoidf_(float x) {
    return 1.0f / (1.0f + expf(-x));
}

__device__ __forceinline__ void gsync() {
    __syncthreads();
    if (threadIdx.x == 0) {
        __threadfence();
        unsigned int gen = *(volatile unsigned int*)&g_gen;
        if (atomicAdd(&g_cnt, 1u) == GRID - 1) {
            *(volatile unsigned int*)&g_cnt = 0u;
            __threadfence();
            *(volatile unsigned int*)&g_gen = gen + 1;
        } else {
            while (*(volatile unsigned int*)&g_gen == gen) __nanosleep(32);
            __threadfence();
        }
    }
    __syncthreads();
}

// stage fp32 vector (coherent read) into half2 smem
__device__ __forceinline__ void stage_h2(half2* dst, const float* src) {
    if (threadIdx.x < 512) {
        float2 v = __ldcg(((const float2*)src) + threadIdx.x);
        dst[threadIdx.x] = __float22half2_rn(v);
    }
}
__device__ __forceinline__ void stage_h2_ro(half2* dst, const float* src) {
    if (threadIdx.x < 512) {
        float2 v = ((const float2*)src)[threadIdx.x];
        dst[threadIdx.x] = __float22half2_rn(v);
    }
}

// load lane's 16 half2 (cols [16L..16L+15] and [16(L+32)..]) into 4 uint4 regs
__device__ __forceinline__ void load_vec(uint4* hv, const half2* shv, int lane) {
    const uint4* s4 = (const uint4*)shv;
    hv[0] = s4[lane * 2];
    hv[1] = s4[lane * 2 + 1];
    hv[2] = s4[(lane + 32) * 2];
    hv[3] = s4[(lane + 32) * 2 + 1];
}

// fp8 row (1024 cols) dot register-cached half2 vector
__device__ __forceinline__ float dot_fp8h(const unsigned char* Wr,
                                          const uint4* hv, int lane)
{
    const uint4* w4 = (const uint4*)Wr;
    uint4 w0 = w4[lane];
    uint4 w1 = w4[lane + 32];
    const __nv_fp8x2_storage_t* p0 = (const __nv_fp8x2_storage_t*)&w0;
    const __nv_fp8x2_storage_t* p1 = (const __nv_fp8x2_storage_t*)&w1;
    const half2* h = (const half2*)hv;
    half2 a0 = __float2half2_rn(0.f);
    half2 a1 = __float2half2_rn(0.f);
#pragma unroll
    for (int k = 0; k < 8; k++) {
        __half2_raw r0 = __nv_cvt_fp8x2_to_halfraw2(p0[k], __NV_E4M3);
        __half2_raw r1 = __nv_cvt_fp8x2_to_halfraw2(p1[k], __NV_E4M3);
        a0 = __hfma2(*(half2*)&r0, h[k],     a0);
        a1 = __hfma2(*(half2*)&r1, h[8 + k], a1);
    }
    float2 f0 = __half22float2(a0);
    float2 f1 = __half22float2(a1);
    return (f0.x + f0.y) + (f1.x + f1.y);
}

__device__ __forceinline__ float dotv(const unsigned char* Wr,
                                      const half2* shv, int lane)
{
    uint4 hv[4];
    load_vec(hv, shv, lane);
    return dot_fp8h(Wr, hv, lane);
}

__device__ __forceinline__ float warp_sum(float v) {
#pragma unroll
    for (int off = 16; off; off >>= 1)
        v += __shfl_xor_sync(0xffffffffu, v, off);
    return v;
}

__device__ __forceinline__ void lse_merge(float& m1, float& s1, int& i1,
                                          float m2, float s2, int i2)
{
    if (m2 > m1)      { s1 = s1 * expf(m1 - m2) + s2; m1 = m2; i1 = i2; }
    else if (m2 == m1){ s1 += s2; if (i2 < i1) i1 = i2; }
    else              { s1 += s2 * expf(m2 - m1); }
}

__device__ __forceinline__ void lstm_update(const float* sg, int ul, float* c_state,
                                            float* h_out, int un,
                                            const float* bih, const float* bhh)
{
    float gi = sg[ul * 4 + 0] + bih[0 * HID + un] + bhh[0 * HID + un];
    float gf = sg[ul * 4 + 1] + bih[1 * HID + un] + bhh[1 * HID + un];
    float gg = sg[ul * 4 + 2] + bih[2 * HID + un] + bhh[2 * HID + un];
    float go = sg[ul * 4 + 3] + bih[3 * HID + un] + bhh[3 * HID + un];
    float i_ = sigmoidf_(gi);
    float f_ = sigmoidf_(gf);
    float g_ = tanhf(gg);
    float o_ = sigmoidf_(go);
    float cn = f_ * (*c_state) + i_ * g_;
    *c_state = cn;
    *h_out   = o_ * tanhf(cn);
}

// ---------------- persistent seq2seq kernel (includes weight conversion) ----------------
__global__ void __launch_bounds__(NT, 1)
seq2seq_kernel(const int* __restrict__ src,
               const float* __restrict__ emb_enc,
               const float* __restrict__ eWih, const float* __restrict__ eWhh,
               const float* __restrict__ enc_bih, const float* __restrict__ enc_bhh,
               const float* __restrict__ emb_dec,
               const float* __restrict__ dWih, const float* __restrict__ dWhh,
               const float* __restrict__ dec_bih, const float* __restrict__ dec_bhh,
               const float* __restrict__ out_W, const float* __restrict__ out_b,
               float* __restrict__ out)
{
    __shared__ half2 sx0[512], sh0[512];
    __shared__ half2 sx1[512], sh1[512];
    __shared__ float sg0[32], sg1[32];
    __shared__ float sc[NL][8];
    __shared__ float swm[32], sws[32];
    __shared__ int   swi[32];
    __shared__ float fm[256], fs[256];
    __shared__ int   fi[256];
    __shared__ int   sflag;

    const int tid  = threadIdx.x;
    const int wib  = tid >> 5;
    const int lane = tid & 31;
    const int bx   = blockIdx.x;
    const bool act = (bx < LBLK);
    const size_t WOFF = (size_t)4 * HID * HID;
    const size_t BOFF = (size_t)4 * HID;

    // ---- pre-phase: fp32 -> fp8 weight conversion (grid-strided) ----
    {
        const size_t stride = (size_t)GRID * NT;
        const size_t base = (size_t)bx * NT + tid;
        for (size_t i = base; i < (size_t)VOCAB * HID / 16; i += stride)
            ((uint4*)d_Wf8)[i] = cvt16_fp8((const float4*)out_W, i);
        const float* srcs[8] = { eWih, eWhh, eWih + WOFF, eWhh + WOFF,
                                 dWih, dWhh, dWih + WOFF, dWhh + WOFF };
#pragma unroll
        for (int m = 0; m < 8; m++)
            for (size_t i = base; i < WOFF / 16; i += stride)
                ((uint4*)d_Lf8[m])[i] = cvt16_fp8((const float4*)srcs[m], i);
        // init state
        int gid = bx * NT + tid;
        if (gid < 2 * HID) { ((float*)d_h0)[gid] = 0.0f; ((float*)d_h1)[gid] = 0.0f; }
        if (tid < 8) { sc[0][tid] = 0.0f; sc[1][tid] = 0.0f; }
        __threadfence();   // every writer fences before the barrier
    }
    gsync();

    const int ul   = wib >> 2;
    const int gate = wib & 3;
    const int unit = bx * 8 + ul;
    const size_t row_off = (size_t)(gate * HID + unit) * HID;

    // ================= encoder: wavefront over layers =================
    for (int k = 0; k <= SEQ; k++) {
        const bool doL0 = act && (k < SEQ);
        const bool doL1 = act && (k >= 1);

        if (doL0) {
            stage_h2_ro(sx0, emb_enc + (size_t)src[k] * HID);
            stage_h2(sh0, &d_h0[k & 1][0]);
        }
        if (doL1) {
            stage_h2(sx1, &d_h0[k & 1][0]);
            stage_h2(sh1, &d_h1[(k - 1) & 1][0]);
        }
        __syncthreads();

        float acc0 = 0.f, acc1 = 0.f;
        if (doL0)
            acc0 = dotv(d_Lf8[0] + row_off, sx0, lane)
                 + dotv(d_Lf8[1] + row_off, sh0, lane);
        if (doL1)
            acc1 = dotv(d_Lf8[2] + row_off, sx1, lane)
                 + dotv(d_Lf8[3] + row_off, sh1, lane);
        acc0 = warp_sum(acc0) * W_INV;
        acc1 = warp_sum(acc1) * W_INV;
        if (lane == 0) { sg0[wib] = acc0; sg1[wib] = acc1; }
        __syncthreads();

        if (tid < 8 && doL0)
            lstm_update(sg0, tid, &sc[0][tid], &d_h0[(k + 1) & 1][bx * 8 + tid],
                        bx * 8 + tid, enc_bih, enc_bhh);
        if (tid >= 8 && tid < 16 && doL1)
            lstm_update(sg1, tid - 8, &sc[1][tid - 8], &d_h1[k & 1][bx * 8 + (tid - 8)],
                        bx * 8 + (tid - 8), enc_bih + BOFF, enc_bhh + BOFF);
        gsync();
    }

    // ================= decoder =================
    for (int t = 0; t < SEQ; t++) {
        const int pr = t & 1;
        const int pw = (t + 1) & 1;

        // ---------- phase A: layer 0 (+ prev logp write) ----------
        if (t > 0) {
            int gid = bx * NT + tid;
            if (gid < VOCAB)
                out[(size_t)(t - 1) * VOCAB + gid] =
                    __ldcg(&d_logits[gid]) - __ldcg(&d_M) - __ldcg(&d_logS);
        }
        {
            int tok = (t == 0) ? BOS : __ldcg(&d_token);
            if (act) {
                stage_h2_ro(sx0, emb_dec + (size_t)tok * HID);
                stage_h2(sh0, &d_h0[pr][0]);
            }
            __syncthreads();

            float acc = 0.f;
            if (act)
                acc = dotv(d_Lf8[4] + row_off, sx0, lane)
                    + dotv(d_Lf8[5] + row_off, sh0, lane);
            acc = warp_sum(acc) * W_INV;
            if (lane == 0) sg0[wib] = acc;
            __syncthreads();
            if (tid < 8 && act)
                lstm_update(sg0, tid, &sc[0][tid], &d_h0[pw][bx * 8 + tid],
                            bx * 8 + tid, dec_bih, dec_bhh);
            gsync();
        }

        // ---------- phase B: layer 1 ----------
        {
            if (act) {
                stage_h2(sx1, &d_h0[pw][0]);
                stage_h2(sh1, &d_h1[pr][0]);
            }
            __syncthreads();

            float acc = 0.f;
            if (act)
                acc = dotv(d_Lf8[6] + row_off, sx1, lane)
                    + dotv(d_Lf8[7] + row_off, sh1, lane);
            acc = warp_sum(acc) * W_INV;
            if (lane == 0) sg1[wib] = acc;
            __syncthreads();
            if (tid < 8 && act)
                lstm_update(sg1, tid, &sc[1][tid], &d_h1[pw][bx * 8 + tid],
                            bx * 8 + tid, dec_bih + BOFF, dec_bhh + BOFF);
            gsync();
        }

        // ---------- phase C: logits (dots first, reductions deferred) ----------
        {
            stage_h2(sh0, &d_h1[pw][0]);
            __syncthreads();

            uint4 hv[4];
            load_vec(hv, sh0, lane);

            float accs[7];
#pragma unroll
            for (int it = 0; it < 7; it++) {
                int row = it * (GRID * 32) + bx * 32 + wib;
                accs[it] = (row < VOCAB)
                    ? dot_fp8h(d_Wf8 + (size_t)row * HID, hv, lane) : 0.f;
            }

            float m = -3.0e38f, s = 0.f;
            int   mi = 0x7fffffff;
#pragma unroll
            for (int it = 0; it < 7; it++) {
                int row = it * (GRID * 32) + bx * 32 + wib;
                if (row < VOCAB) {
                    float acc = warp_sum(accs[it]) * W_INV;
                    if (lane == 0) {
                        acc += out_b[row];
                        d_logits[row] = acc;
                        if (acc > m)       { s = s * expf(m - acc) + 1.f; m = acc; mi = row; }
                        else if (acc == m) { s += 1.f; if (row < mi) mi = row; }
                        else               { s += expf(acc - m); }
                    }
                }
            }
            if (lane == 0) { swm[wib] = m; sws[wib] = s; swi[wib] = mi; }
            __syncthreads();

            unsigned int gen = 0;
            if (tid == 0) {
                float bm = swm[0], bs = sws[0]; int bi = swi[0];
#pragma unroll
                for (int k = 1; k < 32; k++) lse_merge(bm, bs, bi, swm[k], sws[k], swi[k]);
                d_pmax[bx] = bm;
                d_psum[bx] = bs;
                d_pidx[bx] = bi;
                gen = *(volatile unsigned int*)&g_gen;
                __threadfence();
                unsigned int c = atomicAdd(&d_count, 1u);
                sflag = (c == GRID - 1) ? 1 : 0;
            }
            __syncthreads();

            if (sflag) {
                if (tid < 256) {
                    if (tid < GRID) {
                        fm[tid] = __ldcg(&d_pmax[tid]);
                        fs[tid] = __ldcg(&d_psum[tid]);
                        fi[tid] = __ldcg(&d_pidx[tid]);
                    } else {
                        fm[tid] = -3.0e38f; fs[tid] = 0.f; fi[tid] = 0x7fffffff;
                    }
                }
                __syncthreads();
                for (int st = 128; st; st >>= 1) {
                    if (tid < st)
                        lse_merge(fm[tid], fs[tid], fi[tid],
                                  fm[tid + st], fs[tid + st], fi[tid + st]);
                    __syncthreads();
                }
                if (tid == 0) {
                    d_M     = fm[0];
                    d_logS  = logf(fs[0]);
                    d_token = fi[0];
                    *(volatile unsigned int*)&d_count = 0u;
                    __threadfence();
                    *(volatile unsigned int*)&g_gen = gen + 1;
                }
            } else {
                if (tid == 0) {
                    while (*(volatile unsigned int*)&g_gen == gen) __nanosleep(32);
                    __threadfence();
                }
            }
            __syncthreads();
        }
    }

    {
        int gid = bx * NT + tid;
        if (gid < VOCAB)
            out[(size_t)(SEQ - 1) * VOCAB + gid] =
                __ldcg(&d_logits[gid]) - __ldcg(&d_M) - __ldcg(&d_logS);
    }
}

// ---------------- host orchestration: single launch ----------------
extern "C" void kernel_launch(void* const* d_in, const int* in_sizes, int n_in,
                              void* d_out, int out_size)
{
    (void)in_sizes; (void)n_in; (void)out_size;
    const int*   src     = (const int*)  d_in[0];
    const float* emb_enc = (const float*)d_in[2];
    const float* enc_Wih = (const float*)d_in[3];
    const float* enc_Whh = (const float*)d_in[4];
    const float* enc_bih = (const float*)d_in[5];
    const float* enc_bhh = (const float*)d_in[6];
    const float* emb_dec = (const float*)d_in[7];
    const float* dec_Wih = (const float*)d_in[8];
    const float* dec_Whh = (const float*)d_in[9];
    const float* dec_bih = (const float*)d_in[10];
    const float* dec_bhh = (const float*)d_in[11];
    const float* out_W   = (const float*)d_in[12];
    const float* out_b   = (const float*)d_in[13];
    float* out = (float*)d_out;

    seq2seq_kernel<<<GRID, NT>>>(src, emb_enc, enc_Wih, enc_Whh, enc_bih, enc_bhh,
                                 emb_dec, dec_Wih, dec_Whh, dec_bih, dec_bhh,
                                 out_W, out_b, out);
}

// round 13
// speedup vs baseline: 1.1804x; 1.0061x over previous
#include <cuda_runtime.h>
#include <cuda_fp16.h>
#include <cuda_bf16.h>
#include <cuda_fp8.h>
#include <math.h>

#define HID   1024
#define VOCAB 32000
#define SEQ   64
#define NL    2
#define BOS   1
#define GRID  148          // one block per SM
#define LBLK  128          // blocks owning LSTM units (8 units each)
#define NT    1024

#define W_SCALE  64.0f
#define W_INV    (1.0f / 64.0f)

// ---------------- device scratch ----------------
__device__ float d_h0[2][HID];
__device__ float d_h1[2][HID];
__device__ unsigned char d_Wf8[(size_t)VOCAB * HID];   // fp8 out_W
// 0=eWih0 1=eWhh0 2=eWih1 3=eWhh1 4=dWih0 5=dWhh0 6=dWih1 7=dWhh1
__device__ unsigned char d_Lf8[8][(size_t)4 * HID * HID];
__device__ float d_pmax[GRID];
__device__ float d_psum[GRID];
__device__ int   d_pidx[GRID];
__device__ unsigned int d_count = 0;
__device__ int   d_token;
__device__ float d_M, d_logS;
__device__ unsigned int g_gen = 0;
__device__ unsigned int g_cnt = 0;

// ---------------- fp32 -> fp8 ----------------
__device__ __forceinline__ uint4 cvt16_fp8(const float4* s4, size_t i) {
    __nv_fp8x2_storage_t r[8];
#pragma unroll
    for (int k = 0; k < 4; k++) {
        float4 a = s4[4 * i + k];
        float2 lo = make_float2(a.x * W_SCALE, a.y * W_SCALE);
        float2 hi = make_float2(a.z * W_SCALE, a.w * W_SCALE);
        r[2 * k + 0] = __nv_cvt_float2_to_fp8x2(lo, __NV_SATFINITE, __NV_E4M3);
        r[2 * k + 1] = __nv_cvt_float2_to_fp8x2(hi, __NV_SATFINITE, __NV_E4M3);
    }
    return *(uint4*)r;
}

// ---------------- helpers ----------------
__device__ __forceinline__ float sigmoidf_(float x) {
    return 1.0f / (1.0f + expf(-x));
}

__device__ __forceinline__ void gsync() {
    __syncthreads();
    if (threadIdx.x == 0) {
        __threadfence();
        unsigned int gen = *(volatile unsigned int*)&g_gen;
        if (atomicAdd(&g_cnt, 1u) == GRID - 1) {
            *(volatile unsigned int*)&g_cnt = 0u;
            __threadfence();
            *(volatile unsigned int*)&g_gen = gen + 1;
        } else {
            while (*(volatile unsigned int*)&g_gen == gen) __nanosleep(32);
            __threadfence();
        }
    }
    __syncthreads();
}

// stage fp32 vector (coherent read) into half2 smem
__device__ __forceinline__ void stage_h2(half2* dst, const float* src) {
    if (threadIdx.x < 512) {
        float2 v = __ldcg(((const float2*)src) + threadIdx.x);
        dst[threadIdx.x] = __float22half2_rn(v);
    }
}
__device__ __forceinline__ void stage_h2_ro(half2* dst, const float* src) {
    if (threadIdx.x < 512) {
        float2 v = ((const float2*)src)[threadIdx.x];
        dst[threadIdx.x] = __float22half2_rn(v);
    }
}

// load lane's 16 half2 into 4 uint4 regs
__device__ __forceinline__ void load_vec(uint4* hv, const half2* shv, int lane) {
    const uint4* s4 = (const uint4*)shv;
    hv[0] = s4[lane * 2];
    hv[1] = s4[lane * 2 + 1];
    hv[2] = s4[(lane + 32) * 2];
    hv[3] = s4[(lane + 32) * 2 + 1];
}

// fp8 row (1024 cols) dot register-cached half2 vector
__device__ __forceinline__ float dot_fp8h(const unsigned char* Wr,
                                          const uint4* hv, int lane)
{
    const uint4* w4 = (const uint4*)Wr;
    uint4 w0 = w4[lane];
    uint4 w1 = w4[lane + 32];
    const __nv_fp8x2_storage_t* p0 = (const __nv_fp8x2_storage_t*)&w0;
    const __nv_fp8x2_storage_t* p1 = (const __nv_fp8x2_storage_t*)&w1;
    const half2* h = (const half2*)hv;
    half2 a0 = __float2half2_rn(0.f);
    half2 a1 = __float2half2_rn(0.f);
#pragma unroll
    for (int k = 0; k < 8; k++) {
        __half2_raw r0 = __nv_cvt_fp8x2_to_halfraw2(p0[k], __NV_E4M3);
        __half2_raw r1 = __nv_cvt_fp8x2_to_halfraw2(p1[k], __NV_E4M3);
        a0 = __hfma2(*(half2*)&r0, h[k],     a0);
        a1 = __hfma2(*(half2*)&r1, h[8 + k], a1);
    }
    float2 f0 = __half22float2(a0);
    float2 f1 = __half22float2(a1);
    return (f0.x + f0.y) + (f1.x + f1.y);
}

__device__ __forceinline__ float dotv(const unsigned char* Wr,
                                      const half2* shv, int lane)
{
    uint4 hv[4];
    load_vec(hv, shv, lane);
    return dot_fp8h(Wr, hv, lane);
}

__device__ __forceinline__ float warp_sum(float v) {
#pragma unroll
    for (int off = 16; off; off >>= 1)
        v += __shfl_xor_sync(0xffffffffu, v, off);
    return v;
}

__device__ __forceinline__ void lse_merge(float& m1, float& s1, int& i1,
                                          float m2, float s2, int i2)
{
    if (m2 > m1)      { s1 = s1 * expf(m1 - m2) + s2; m1 = m2; i1 = i2; }
    else if (m2 == m1){ s1 += s2; if (i2 < i1) i1 = i2; }
    else              { s1 += s2 * expf(m2 - m1); }
}

__device__ __forceinline__ void lstm_update(const float* sg, int ul, float* c_state,
                                            float* h_out, int un,
                                            const float* bih, const float* bhh)
{
    float gi = sg[ul * 4 + 0] + bih[0 * HID + un] + bhh[0 * HID + un];
    float gf = sg[ul * 4 + 1] + bih[1 * HID + un] + bhh[1 * HID + un];
    float gg = sg[ul * 4 + 2] + bih[2 * HID + un] + bhh[2 * HID + un];
    float go = sg[ul * 4 + 3] + bih[3 * HID + un] + bhh[3 * HID + un];
    float i_ = sigmoidf_(gi);
    float f_ = sigmoidf_(gf);
    float g_ = tanhf(gg);
    float o_ = sigmoidf_(go);
    float cn = f_ * (*c_state) + i_ * g_;
    *c_state = cn;
    *h_out   = o_ * tanhf(cn);
}

// ---------------- persistent seq2seq kernel ----------------
__global__ void __launch_bounds__(NT, 1)
seq2seq_kernel(const int* __restrict__ src,
               const float* __restrict__ emb_enc,
               const float* __restrict__ eWih, const float* __restrict__ eWhh,
               const float* __restrict__ enc_bih, const float* __restrict__ enc_bhh,
               const float* __restrict__ emb_dec,
               const float* __restrict__ dWih, const float* __restrict__ dWhh,
               const float* __restrict__ dec_bih, const float* __restrict__ dec_bhh,
               const float* __restrict__ out_W, const float* __restrict__ out_b,
               float* __restrict__ out)
{
    __shared__ half2 sx0[512], sh0[512];
    __shared__ half2 sx1[512], sh1[512];
    __shared__ float sg0[32], sg1[32];
    __shared__ float sgh0[32], sgh1[32];   // precomputed Whh gate partials
    __shared__ float sc[NL][8];
    __shared__ float swm[32], sws[32];
    __shared__ int   swi[32];
    __shared__ float fm[256], fs[256];
    __shared__ int   fi[256];
    __shared__ int   sflag;

    const int tid  = threadIdx.x;
    const int wib  = tid >> 5;
    const int lane = tid & 31;
    const int bx   = blockIdx.x;
    const bool act = (bx < LBLK);
    const size_t WOFF = (size_t)4 * HID * HID;
    const size_t BOFF = (size_t)4 * HID;

    // ---- pre-phase: fp32 -> fp8 weight conversion (grid-strided) + init ----
    {
        const size_t stride = (size_t)GRID * NT;
        const size_t base = (size_t)bx * NT + tid;
        for (size_t i = base; i < (size_t)VOCAB * HID / 16; i += stride)
            ((uint4*)d_Wf8)[i] = cvt16_fp8((const float4*)out_W, i);
        const float* srcs[8] = { eWih, eWhh, eWih + WOFF, eWhh + WOFF,
                                 dWih, dWhh, dWih + WOFF, dWhh + WOFF };
#pragma unroll
        for (int m = 0; m < 8; m++)
            for (size_t i = base; i < WOFF / 16; i += stride)
                ((uint4*)d_Lf8[m])[i] = cvt16_fp8((const float4*)srcs[m], i);
        int gid = bx * NT + tid;
        if (gid < 2 * HID) { ((float*)d_h0)[gid] = 0.0f; ((float*)d_h1)[gid] = 0.0f; }
        if (tid < 8) { sc[0][tid] = 0.0f; sc[1][tid] = 0.0f; }
        __threadfence();
    }
    gsync();

    const int ul   = wib >> 2;
    const int gate = wib & 3;
    const int unit = bx * 8 + ul;
    const size_t row_off = (size_t)(gate * HID + unit) * HID;

    // ================= encoder: wavefront over layers =================
    for (int k = 0; k <= SEQ; k++) {
        const bool doL0 = act && (k < SEQ);
        const bool doL1 = act && (k >= 1);

        if (doL0) {
            stage_h2_ro(sx0, emb_enc + (size_t)src[k] * HID);
            stage_h2(sh0, &d_h0[k & 1][0]);
        }
        if (doL1) {
            stage_h2(sx1, &d_h0[k & 1][0]);
            stage_h2(sh1, &d_h1[(k - 1) & 1][0]);
        }
        __syncthreads();

        float acc0 = 0.f, acc1 = 0.f;
        if (doL0)
            acc0 = dotv(d_Lf8[0] + row_off, sx0, lane)
                 + dotv(d_Lf8[1] + row_off, sh0, lane);
        if (doL1)
            acc1 = dotv(d_Lf8[2] + row_off, sx1, lane)
                 + dotv(d_Lf8[3] + row_off, sh1, lane);
        acc0 = warp_sum(acc0) * W_INV;
        acc1 = warp_sum(acc1) * W_INV;
        if (lane == 0) { sg0[wib] = acc0; sg1[wib] = acc1; }
        __syncthreads();

        if (tid < 8 && doL0)
            lstm_update(sg0, tid, &sc[0][tid], &d_h0[(k + 1) & 1][bx * 8 + tid],
                        bx * 8 + tid, enc_bih, enc_bhh);
        if (tid >= 8 && tid < 16 && doL1)
            lstm_update(sg1, tid - 8, &sc[1][tid - 8], &d_h1[k & 1][bx * 8 + (tid - 8)],
                        bx * 8 + (tid - 8), enc_bih + BOFF, enc_bhh + BOFF);
        gsync();
    }
    // encoder final: h0 = d_h0[0], h1 = d_h1[0]

    // ---- seed sgh0/sgh1 for decoder t=0 (block-local, no barrier) ----
    if (act) {
        stage_h2(sx1, &d_h0[0][0]);
        stage_h2(sh1, &d_h1[0][0]);
        __syncthreads();
        float g0 = dotv(d_Lf8[5] + row_off, sx1, lane);
        float g1 = dotv(d_Lf8[7] + row_off, sh1, lane);
        g0 = warp_sum(g0) * W_INV;
        g1 = warp_sum(g1) * W_INV;
        if (lane == 0) { sgh0[wib] = g0; sgh1[wib] = g1; }
        __syncthreads();
    }

    // ================= decoder =================
    for (int t = 0; t < SEQ; t++) {
        const int pw = (t + 1) & 1;

        // ---------- phase A: layer 0 = Wih0 @ x  (+ sgh0 recurrent part) ----------
        {
            int tok = (t == 0) ? BOS : __ldcg(&d_token);
            if (act) stage_h2_ro(sx0, emb_dec + (size_t)tok * HID);
            __syncthreads();

            float acc = 0.f;
            if (act) acc = dotv(d_Lf8[4] + row_off, sx0, lane);
            acc = warp_sum(acc) * W_INV;
            if (lane == 0) sg0[wib] = acc + sgh0[wib];
            __syncthreads();
            if (tid < 8 && act)
                lstm_update(sg0, tid, &sc[0][tid], &d_h0[pw][bx * 8 + tid],
                            bx * 8 + tid, dec_bih, dec_bhh);
            gsync();
        }

        // ---------- phase B: layer 1 = Wih1 @ h0_new (+ sgh1) ----------
        {
            if (act) stage_h2(sx1, &d_h0[pw][0]);
            __syncthreads();

            float acc = 0.f;
            if (act) acc = dotv(d_Lf8[6] + row_off, sx1, lane);
            acc = warp_sum(acc) * W_INV;
            if (lane == 0) sg1[wib] = acc + sgh1[wib];
            __syncthreads();
            if (tid < 8 && act)
                lstm_update(sg1, tid, &sc[1][tid], &d_h1[pw][bx * 8 + tid],
                            bx * 8 + tid, dec_bih + BOFF, dec_bhh + BOFF);
            gsync();
        }

        // ---------- phase C: logits + overlap Whh dots + fused finalize ----------
        {
            stage_h2(sh0, &d_h1[pw][0]);   // logits vector + Whh1 input
            // sx1 still holds h0(pw) from phase B (act blocks) — Whh0 input
            __syncthreads();

            uint4 hv[4];
            load_vec(hv, sh0, lane);

            float accs[7];
#pragma unroll
            for (int it = 0; it < 7; it++) {
                int row = it * (GRID * 32) + bx * 32 + wib;
                accs[it] = (row < VOCAB)
                    ? dot_fp8h(d_Wf8 + (size_t)row * HID, hv, lane) : 0.f;
            }

            float logitv[7];
            float m = -3.0e38f, s = 0.f;
            int   mi = 0x7fffffff;
#pragma unroll
            for (int it = 0; it < 7; it++) {
                int row = it * (GRID * 32) + bx * 32 + wib;
                float acc = warp_sum(accs[it]) * W_INV;
                if (lane == 0 && row < VOCAB) {
                    acc += out_b[row];
                    logitv[it] = acc;
                    if (acc > m)       { s = s * expf(m - acc) + 1.f; m = acc; mi = row; }
                    else if (acc == m) { s += 1.f; if (row < mi) mi = row; }
                    else               { s += expf(acc - m); }
                }
            }
            if (lane == 0) { swm[wib] = m; sws[wib] = s; swi[wib] = mi; }
            __syncthreads();

            unsigned int gen = 0;
            if (tid == 0) {
                float bm = swm[0], bs = sws[0]; int bi = swi[0];
#pragma unroll
                for (int k = 1; k < 32; k++) lse_merge(bm, bs, bi, swm[k], sws[k], swi[k]);
                d_pmax[bx] = bm;
                d_psum[bx] = bs;
                d_pidx[bx] = bi;
                gen = *(volatile unsigned int*)&g_gen;
                __threadfence();
                unsigned int c = atomicAdd(&d_count, 1u);
                sflag = (c == GRID - 1) ? 1 : 0;
            }
            __syncthreads();

            if (sflag) {
                // last block: global finalize, then release the barrier
                if (tid < 256) {
                    if (tid < GRID) {
                        fm[tid] = __ldcg(&d_pmax[tid]);
                        fs[tid] = __ldcg(&d_psum[tid]);
                        fi[tid] = __ldcg(&d_pidx[tid]);
                    } else {
                        fm[tid] = -3.0e38f; fs[tid] = 0.f; fi[tid] = 0x7fffffff;
                    }
                }
                __syncthreads();
                for (int st = 128; st; st >>= 1) {
                    if (tid < st)
                        lse_merge(fm[tid], fs[tid], fi[tid],
                                  fm[tid + st], fs[tid + st], fi[tid + st]);
                    __syncthreads();
                }
                if (tid == 0) {
                    d_M     = fm[0];
                    d_logS  = logf(fs[0]);
                    d_token = fi[0];
                    *(volatile unsigned int*)&d_count = 0u;
                    __threadfence();
                    *(volatile unsigned int*)&g_gen = gen + 1;
                }
            }

            // overlap: next step's Whh gate partials (token-independent)
            if (act && t < SEQ - 1) {
                float g0 = dotv(d_Lf8[5] + row_off, sx1, lane);   // Whh0 @ h0(t+1)
                float g1 = dotv(d_Lf8[7] + row_off, sh0, lane);   // Whh1 @ h1(t+1)
                g0 = warp_sum(g0) * W_INV;
                g1 = warp_sum(g1) * W_INV;
                if (lane == 0) { sgh0[wib] = g0; sgh1[wib] = g1; }
            }

            if (tid == 0 && !sflag) {
                while (*(volatile unsigned int*)&g_gen == gen) __nanosleep(32);
                __threadfence();
            }
            __syncthreads();

            // write this step's log-probs directly from registers
            {
                float M = __ldcg(&d_M);
                float L = __ldcg(&d_logS);
                if (lane == 0) {
#pragma unroll
                    for (int it = 0; it < 7; it++) {
                        int row = it * (GRID * 32) + bx * 32 + wib;
                        if (row < VOCAB)
                            out[(size_t)t * VOCAB + row] = logitv[it] - M - L;
                    }
                }
            }
        }
    }
}

// ---------------- host orchestration: single launch ----------------
extern "C" void kernel_launch(void* const* d_in, const int* in_sizes, int n_in,
                              void* d_out, int out_size)
{
    (void)in_sizes; (void)n_in; (void)out_size;
    const int*   src     = (const int*)  d_in[0];
    const float* emb_enc = (const float*)d_in[2];
    const float* enc_Wih = (const float*)d_in[3];
    const float* enc_Whh = (const float*)d_in[4];
    const float* enc_bih = (const float*)d_in[5];
    const float* enc_bhh = (const float*)d_in[6];
    const float* emb_dec = (const float*)d_in[7];
    const float* dec_Wih = (const float*)d_in[8];
    const float* dec_Whh = (const float*)d_in[9];
    const float* dec_bih = (const float*)d_in[10];
    const float* dec_bhh = (const float*)d_in[11];
    const float* out_W   = (const float*)d_in[12];
    const float* out_b   = (const float*)d_in[13];
    float* out = (float*)d_out;

    seq2seq_kernel<<<GRID, NT>>>(src, emb_enc, enc_Wih, enc_Whh, enc_bih, enc_bhh,
                                 emb_dec, dec_Wih, dec_Whh, dec_bih, dec_bhh,
                                 out_W, out_b, out);
}

// round 14
// speedup vs baseline: 1.2165x; 1.0306x over previous
#include <cuda_runtime.h>
#include <cuda_fp16.h>
#include <cuda_bf16.h>
#include <cuda_fp8.h>
#include <math.h>

#define HID   1024
#define VOCAB 32000
#define SEQ   64
#define NL    2
#define BOS   1
#define GRID  148          // one block per SM
#define LBLK  128          // blocks owning LSTM units (8 units each)
#define NT    1024

#define W_SCALE  64.0f
#define W_INV    (1.0f / 64.0f)

// ---------------- device scratch ----------------
__device__ float d_h0[2][HID];
__device__ float d_h1[2][HID];
__device__ unsigned char d_Wf8[(size_t)VOCAB * HID];   // fp8 out_W
// 0=eWih0 1=eWhh0 2=eWih1 3=eWhh1 4=dWih0 5=dWhh0 6=dWih1 7=dWhh1
__device__ unsigned char d_Lf8[8][(size_t)4 * HID * HID];
__device__ float d_pmax[GRID];
__device__ float d_psum[GRID];
__device__ int   d_pidx[GRID];
__device__ unsigned int d_count = 0;
__device__ int   d_token;
__device__ float d_M, d_logS;
__device__ unsigned int g_gen = 0;   // full-grid barrier
__device__ unsigned int g_cnt = 0;
__device__ unsigned int l_gen = 0;   // LSTM-subgroup barrier (LBLK blocks)
__device__ unsigned int l_cnt = 0;

// ---------------- acquire/release primitives ----------------
__device__ __forceinline__ unsigned int atom_add_release(unsigned int* p, unsigned int v) {
    unsigned int old;
    asm volatile("atom.add.release.gpu.global.u32 %0, [%1], %2;"
                 : "=r"(old) : "l"(p), "r"(v) : "memory");
    return old;
}
__device__ __forceinline__ unsigned int ld_acquire(unsigned int* p) {
    unsigned int v;
    asm volatile("ld.acquire.gpu.global.u32 %0, [%1];" : "=r"(v) : "l"(p) : "memory");
    return v;
}
__device__ __forceinline__ void st_release(unsigned int* p, unsigned int v) {
    asm volatile("st.release.gpu.global.u32 [%0], %1;" :: "l"(p), "r"(v) : "memory");
}
__device__ __forceinline__ void st_relaxed(unsigned int* p, unsigned int v) {
    asm volatile("st.relaxed.gpu.global.u32 [%0], %1;" :: "l"(p), "r"(v) : "memory");
}

// full-grid barrier
__device__ __forceinline__ void gsync() {
    __syncthreads();
    if (threadIdx.x == 0) {
        unsigned int gen = ld_acquire(&g_gen);
        if (atom_add_release(&g_cnt, 1u) == GRID - 1) {
            st_relaxed(&g_cnt, 0u);
            st_release(&g_gen, gen + 1);
        } else {
            while (ld_acquire(&g_gen) == gen) { }
        }
    }
    __syncthreads();
}
// LSTM-subgroup barrier (only blocks bx < LBLK call this)
__device__ __forceinline__ void gsyncL() {
    __syncthreads();
    if (threadIdx.x == 0) {
        unsigned int gen = ld_acquire(&l_gen);
        if (atom_add_release(&l_cnt, 1u) == LBLK - 1) {
            st_relaxed(&l_cnt, 0u);
            st_release(&l_gen, gen + 1);
        } else {
            while (ld_acquire(&l_gen) == gen) { }
        }
    }
    __syncthreads();
}

// ---------------- fp32 -> fp8 ----------------
__device__ __forceinline__ uint4 cvt16_fp8(const float4* s4, size_t i) {
    __nv_fp8x2_storage_t r[8];
#pragma unroll
    for (int k = 0; k < 4; k++) {
        float4 a = s4[4 * i + k];
        float2 lo = make_float2(a.x * W_SCALE, a.y * W_SCALE);
        float2 hi = make_float2(a.z * W_SCALE, a.w * W_SCALE);
        r[2 * k + 0] = __nv_cvt_float2_to_fp8x2(lo, __NV_SATFINITE, __NV_E4M3);
        r[2 * k + 1] = __nv_cvt_float2_to_fp8x2(hi, __NV_SATFINITE, __NV_E4M3);
    }
    return *(uint4*)r;
}

// ---------------- helpers ----------------
__device__ __forceinline__ float sigmoidf_(float x) {
    return 1.0f / (1.0f + expf(-x));
}

__device__ __forceinline__ void stage_h2(half2* dst, const float* src) {
    if (threadIdx.x < 512) {
        float2 v = __ldcg(((const float2*)src) + threadIdx.x);
        dst[threadIdx.x] = __float22half2_rn(v);
    }
}
__device__ __forceinline__ void stage_h2_ro(half2* dst, const float* src) {
    if (threadIdx.x < 512) {
        float2 v = ((const float2*)src)[threadIdx.x];
        dst[threadIdx.x] = __float22half2_rn(v);
    }
}

__device__ __forceinline__ void load_vec(uint4* hv, const half2* shv, int lane) {
    const uint4* s4 = (const uint4*)shv;
    hv[0] = s4[lane * 2];
    hv[1] = s4[lane * 2 + 1];
    hv[2] = s4[(lane + 32) * 2];
    hv[3] = s4[(lane + 32) * 2 + 1];
}

// fp8 row dot register-cached half2 vector; L1-cached weight loads (LSTM rows)
__device__ __forceinline__ float dot_fp8h(const unsigned char* Wr,
                                          const uint4* hv, int lane)
{
    const uint4* w4 = (const uint4*)Wr;
    uint4 w0 = w4[lane];
    uint4 w1 = w4[lane + 32];
    const __nv_fp8x2_storage_t* p0 = (const __nv_fp8x2_storage_t*)&w0;
    const __nv_fp8x2_storage_t* p1 = (const __nv_fp8x2_storage_t*)&w1;
    const half2* h = (const half2*)hv;
    half2 a0 = __float2half2_rn(0.f);
    half2 a1 = __float2half2_rn(0.f);
#pragma unroll
    for (int k = 0; k < 8; k++) {
        __half2_raw r0 = __nv_cvt_fp8x2_to_halfraw2(p0[k], __NV_E4M3);
        __half2_raw r1 = __nv_cvt_fp8x2_to_halfraw2(p1[k], __NV_E4M3);
        a0 = __hfma2(*(half2*)&r0, h[k],     a0);
        a1 = __hfma2(*(half2*)&r1, h[8 + k], a1);
    }
    float2 f0 = __half22float2(a0);
    float2 f1 = __half22float2(a1);
    return (f0.x + f0.y) + (f1.x + f1.y);
}

// L2-only weight loads (logits rows — don't pollute L1)
__device__ __forceinline__ float dot_fp8h_cg(const unsigned char* Wr,
                                             const uint4* hv, int lane)
{
    const uint4* w4 = (const uint4*)Wr;
    uint4 w0 = __ldcg(w4 + lane);
    uint4 w1 = __ldcg(w4 + lane + 32);
    const __nv_fp8x2_storage_t* p0 = (const __nv_fp8x2_storage_t*)&w0;
    const __nv_fp8x2_storage_t* p1 = (const __nv_fp8x2_storage_t*)&w1;
    const half2* h = (const half2*)hv;
    half2 a0 = __float2half2_rn(0.f);
    half2 a1 = __float2half2_rn(0.f);
#pragma unroll
    for (int k = 0; k < 8; k++) {
        __half2_raw r0 = __nv_cvt_fp8x2_to_halfraw2(p0[k], __NV_E4M3);
        __half2_raw r1 = __nv_cvt_fp8x2_to_halfraw2(p1[k], __NV_E4M3);
        a0 = __hfma2(*(half2*)&r0, h[k],     a0);
        a1 = __hfma2(*(half2*)&r1, h[8 + k], a1);
    }
    float2 f0 = __half22float2(a0);
    float2 f1 = __half22float2(a1);
    return (f0.x + f0.y) + (f1.x + f1.y);
}

__device__ __forceinline__ float dotv(const unsigned char* Wr,
                                      const half2* shv, int lane)
{
    uint4 hv[4];
    load_vec(hv, shv, lane);
    return dot_fp8h(Wr, hv, lane);
}

__device__ __forceinline__ float warp_sum(float v) {
#pragma unroll
    for (int off = 16; off; off >>= 1)
        v += __shfl_xor_sync(0xffffffffu, v, off);
    return v;
}

__device__ __forceinline__ void lse_merge(float& m1, float& s1, int& i1,
                                          float m2, float s2, int i2)
{
    if (m2 > m1)      { s1 = s1 * expf(m1 - m2) + s2; m1 = m2; i1 = i2; }
    else if (m2 == m1){ s1 += s2; if (i2 < i1) i1 = i2; }
    else              { s1 += s2 * expf(m2 - m1); }
}

__device__ __forceinline__ void lstm_update(const float* sg, int ul, float* c_state,
                                            float* h_out, int un,
                                            const float* bih, const float* bhh)
{
    float gi = sg[ul * 4 + 0] + bih[0 * HID + un] + bhh[0 * HID + un];
    float gf = sg[ul * 4 + 1] + bih[1 * HID + un] + bhh[1 * HID + un];
    float gg = sg[ul * 4 + 2] + bih[2 * HID + un] + bhh[2 * HID + un];
    float go = sg[ul * 4 + 3] + bih[3 * HID + un] + bhh[3 * HID + un];
    float i_ = sigmoidf_(gi);
    float f_ = sigmoidf_(gf);
    float g_ = tanhf(gg);
    float o_ = sigmoidf_(go);
    float cn = f_ * (*c_state) + i_ * g_;
    *c_state = cn;
    *h_out   = o_ * tanhf(cn);
}

// ---------------- persistent seq2seq kernel ----------------
__global__ void __launch_bounds__(NT, 1)
seq2seq_kernel(const int* __restrict__ src,
               const float* __restrict__ emb_enc,
               const float* __restrict__ eWih, const float* __restrict__ eWhh,
               const float* __restrict__ enc_bih, const float* __restrict__ enc_bhh,
               const float* __restrict__ emb_dec,
               const float* __restrict__ dWih, const float* __restrict__ dWhh,
               const float* __restrict__ dec_bih, const float* __restrict__ dec_bhh,
               const float* __restrict__ out_W, const float* __restrict__ out_b,
               float* __restrict__ out)
{
    __shared__ half2 sx0[512], sh0[512];
    __shared__ half2 sx1[512], sh1[512];
    __shared__ float sg0[32], sg1[32];
    __shared__ float sgh0[32], sgh1[32];
    __shared__ float sc[NL][8];
    __shared__ float swm[32], sws[32];
    __shared__ int   swi[32];
    __shared__ float fm[256], fs[256];
    __shared__ int   fi[256];
    __shared__ int   sflag;

    const int tid  = threadIdx.x;
    const int wib  = tid >> 5;
    const int lane = tid & 31;
    const int bx   = blockIdx.x;
    const bool act = (bx < LBLK);
    const size_t WOFF = (size_t)4 * HID * HID;
    const size_t BOFF = (size_t)4 * HID;

    // ---- pre-phase: fp32 -> fp8 weight conversion + init ----
    {
        const size_t stride = (size_t)GRID * NT;
        const size_t base = (size_t)bx * NT + tid;
        for (size_t i = base; i < (size_t)VOCAB * HID / 16; i += stride)
            ((uint4*)d_Wf8)[i] = cvt16_fp8((const float4*)out_W, i);
        const float* srcs[8] = { eWih, eWhh, eWih + WOFF, eWhh + WOFF,
                                 dWih, dWhh, dWih + WOFF, dWhh + WOFF };
#pragma unroll
        for (int m = 0; m < 8; m++)
            for (size_t i = base; i < WOFF / 16; i += stride)
                ((uint4*)d_Lf8[m])[i] = cvt16_fp8((const float4*)srcs[m], i);
        int gid = bx * NT + tid;
        if (gid < 2 * HID) { ((float*)d_h0)[gid] = 0.0f; ((float*)d_h1)[gid] = 0.0f; }
        if (tid < 8) { sc[0][tid] = 0.0f; sc[1][tid] = 0.0f; }
    }
    gsync();   // release-arrival publishes all conversions

    const int ul   = wib >> 2;
    const int gate = wib & 3;
    const int unit = bx * 8 + ul;
    const size_t row_off = (size_t)(gate * HID + unit) * HID;

    // preload out_b for this warp's 7 logits rows
    float bv[7];
#pragma unroll
    for (int it = 0; it < 7; it++) {
        int row = it * (GRID * 32) + bx * 32 + wib;
        bv[it] = (lane == 0 && row < VOCAB) ? out_b[row] : 0.f;
    }

    // ================= encoder (LSTM blocks only; sub-barriers) =================
    if (act) {
        for (int k = 0; k <= SEQ; k++) {
            const bool doL0 = (k < SEQ);
            const bool doL1 = (k >= 1);

            if (doL0) {
                stage_h2_ro(sx0, emb_enc + (size_t)src[k] * HID);
                stage_h2(sh0, &d_h0[k & 1][0]);
            }
            if (doL1) {
                stage_h2(sx1, &d_h0[k & 1][0]);
                stage_h2(sh1, &d_h1[(k - 1) & 1][0]);
            }
            __syncthreads();

            float acc0 = 0.f, acc1 = 0.f;
            if (doL0)
                acc0 = dotv(d_Lf8[0] + row_off, sx0, lane)
                     + dotv(d_Lf8[1] + row_off, sh0, lane);
            if (doL1)
                acc1 = dotv(d_Lf8[2] + row_off, sx1, lane)
                     + dotv(d_Lf8[3] + row_off, sh1, lane);
            acc0 = warp_sum(acc0) * W_INV;
            acc1 = warp_sum(acc1) * W_INV;
            if (lane == 0) { sg0[wib] = acc0; sg1[wib] = acc1; }
            __syncthreads();

            if (tid < 8 && doL0)
                lstm_update(sg0, tid, &sc[0][tid], &d_h0[(k + 1) & 1][bx * 8 + tid],
                            bx * 8 + tid, enc_bih, enc_bhh);
            if (tid >= 8 && tid < 16 && doL1)
                lstm_update(sg1, tid - 8, &sc[1][tid - 8], &d_h1[k & 1][bx * 8 + (tid - 8)],
                            bx * 8 + (tid - 8), enc_bih + BOFF, enc_bhh + BOFF);
            gsyncL();
        }

        // seed sgh0/sgh1 for decoder t=0 (block-local)
        stage_h2(sx1, &d_h0[0][0]);
        stage_h2(sh1, &d_h1[0][0]);
        __syncthreads();
        float g0 = dotv(d_Lf8[5] + row_off, sx1, lane);
        float g1 = dotv(d_Lf8[7] + row_off, sh1, lane);
        g0 = warp_sum(g0) * W_INV;
        g1 = warp_sum(g1) * W_INV;
        if (lane == 0) { sgh0[wib] = g0; sgh1[wib] = g1; }
        __syncthreads();
    }

    // ================= decoder =================
    for (int t = 0; t < SEQ; t++) {
        const int pw = (t + 1) & 1;

        // ---------- phase A: layer 0 (LSTM blocks only; sub-barrier) ----------
        if (act) {
            int tok = (t == 0) ? BOS : __ldcg(&d_token);
            stage_h2_ro(sx0, emb_dec + (size_t)tok * HID);
            __syncthreads();

            float acc = dotv(d_Lf8[4] + row_off, sx0, lane);
            acc = warp_sum(acc) * W_INV;
            if (lane == 0) sg0[wib] = acc + sgh0[wib];
            __syncthreads();
            if (tid < 8)
                lstm_update(sg0, tid, &sc[0][tid], &d_h0[pw][bx * 8 + tid],
                            bx * 8 + tid, dec_bih, dec_bhh);
            gsyncL();

            // ---------- phase B: layer 1 ----------
            stage_h2(sx1, &d_h0[pw][0]);
            __syncthreads();

            acc = dotv(d_Lf8[6] + row_off, sx1, lane);
            acc = warp_sum(acc) * W_INV;
            if (lane == 0) sg1[wib] = acc + sgh1[wib];
            __syncthreads();
            if (tid < 8)
                lstm_update(sg1, tid, &sc[1][tid], &d_h1[pw][bx * 8 + tid],
                            bx * 8 + tid, dec_bih + BOFF, dec_bhh + BOFF);
        }
        gsync();   // full grid: h1_new published for logits

        // ---------- phase C: logits + overlap Whh dots + fused finalize ----------
        {
            stage_h2(sh0, &d_h1[pw][0]);
            __syncthreads();

            uint4 hv[4];
            load_vec(hv, sh0, lane);

            float accs[7];
#pragma unroll
            for (int it = 0; it < 7; it++) {
                int row = it * (GRID * 32) + bx * 32 + wib;
                accs[it] = (row < VOCAB)
                    ? dot_fp8h_cg(d_Wf8 + (size_t)row * HID, hv, lane) : 0.f;
            }

            float logitv[7];
            float m = -3.0e38f, s = 0.f;
            int   mi = 0x7fffffff;
#pragma unroll
            for (int it = 0; it < 7; it++) {
                int row = it * (GRID * 32) + bx * 32 + wib;
                float acc = warp_sum(accs[it]) * W_INV;
                if (lane == 0 && row < VOCAB) {
                    acc += bv[it];
                    logitv[it] = acc;
                    if (acc > m)       { s = s * expf(m - acc) + 1.f; m = acc; mi = row; }
                    else if (acc == m) { s += 1.f; if (row < mi) mi = row; }
                    else               { s += expf(acc - m); }
                }
            }
            if (lane == 0) { swm[wib] = m; sws[wib] = s; swi[wib] = mi; }
            __syncthreads();

            unsigned int gen = 0;
            if (tid == 0) {
                float bm = swm[0], bs = sws[0]; int bi = swi[0];
#pragma unroll
                for (int k = 1; k < 32; k++) lse_merge(bm, bs, bi, swm[k], sws[k], swi[k]);
                d_pmax[bx] = bm;
                d_psum[bx] = bs;
                d_pidx[bx] = bi;
                gen = ld_acquire(&g_gen);
                sflag = (atom_add_release(&d_count, 1u) == GRID - 1) ? 1 : 0;
            }
            __syncthreads();

            if (sflag) {
                if (tid < 256) {
                    if (tid < GRID) {
                        fm[tid] = __ldcg(&d_pmax[tid]);
                        fs[tid] = __ldcg(&d_psum[tid]);
                        fi[tid] = __ldcg(&d_pidx[tid]);
                    } else {
                        fm[tid] = -3.0e38f; fs[tid] = 0.f; fi[tid] = 0x7fffffff;
                    }
                }
                __syncthreads();
                for (int st = 128; st; st >>= 1) {
                    if (tid < st)
                        lse_merge(fm[tid], fs[tid], fi[tid],
                                  fm[tid + st], fs[tid + st], fi[tid + st]);
                    __syncthreads();
                }
                if (tid == 0) {
                    d_M     = fm[0];
                    d_logS  = logf(fs[0]);
                    d_token = fi[0];
                    st_relaxed(&d_count, 0u);
                    st_release(&g_gen, gen + 1);
                }
            }

            // overlap: next step's Whh gate partials (token-independent)
            if (act && t < SEQ - 1) {
                float g0 = dotv(d_Lf8[5] + row_off, sx1, lane);   // Whh0 @ h0(t+1)
                float g1 = dotv(d_Lf8[7] + row_off, sh0, lane);   // Whh1 @ h1(t+1)
                g0 = warp_sum(g0) * W_INV;
                g1 = warp_sum(g1) * W_INV;
                if (lane == 0) { sgh0[wib] = g0; sgh1[wib] = g1; }
            }

            if (tid == 0 && !sflag) {
                while (ld_acquire(&g_gen) == gen) { }
            }
            __syncthreads();

            // write this step's log-probs directly from registers
            {
                float M = __ldcg(&d_M);
                float L = __ldcg(&d_logS);
                if (lane == 0) {
#pragma unroll
                    for (int it = 0; it < 7; it++) {
                        int row = it * (GRID * 32) + bx * 32 + wib;
                        if (row < VOCAB)
                            out[(size_t)t * VOCAB + row] = logitv[it] - M - L;
                    }
                }
            }
        }
    }
}

// ---------------- host orchestration: single launch ----------------
extern "C" void kernel_launch(void* const* d_in, const int* in_sizes, int n_in,
                              void* d_out, int out_size)
{
    (void)in_sizes; (void)n_in; (void)out_size;
    const int*   src     = (const int*)  d_in[0];
    const float* emb_enc = (const float*)d_in[2];
    const float* enc_Wih = (const float*)d_in[3];
    const float* enc_Whh = (const float*)d_in[4];
    const float* enc_bih = (const float*)d_in[5];
    const float* enc_bhh = (const float*)d_in[6];
    const float* emb_dec = (const float*)d_in[7];
    const float* dec_Wih = (const float*)d_in[8];
    const float* dec_Whh = (const float*)d_in[9];
    const float* dec_bih = (const float*)d_in[10];
    const float* dec_bhh = (const float*)d_in[11];
    const float* out_W   = (const float*)d_in[12];
    const float* out_b   = (const float*)d_in[13];
    float* out = (float*)d_out;

    seq2seq_kernel<<<GRID, NT>>>(src, emb_enc, enc_Wih, enc_Whh, enc_bih, enc_bhh,
                                 emb_dec, dec_Wih, dec_Whh, dec_bih, dec_bhh,
                                 out_W, out_b, out);
}